// round 1
// baseline (speedup 1.0000x reference)
#include <cuda_runtime.h>
#include <math.h>

#define NN 20000
#define EE 320000
#define HH 256
#define LL 6
#define GB 20
#define PG 1000

// ---------------- scratch (static device allocations are permitted) --------
__device__ float g_R[EE * HH];          // relu(edge_attr@ew1+eb1)   327.7 MB
__device__ float g_W[LL * HH * HH];     // folded ew2@lin_w[l]
__device__ float g_bl[LL * HH];         // folded bias
__device__ float g_h[NN * HH];
__device__ float g_z[NN * HH];
__device__ float g_t[NN * HH];
__device__ float g_hn[NN * HH];
__device__ float g_scores[NN];
__device__ float g_attn[NN];
__device__ float g_stats[2];
__device__ float g_pooled[GB * HH];

__device__ __forceinline__ float siluf(float x) { return x / (1.f + expf(-x)); }

// ---------------- weight folding: W_l = ew2 @ lin_w[l] ---------------------
__global__ void prep_W(const float* __restrict__ ew2, const float* __restrict__ lin_w) {
    int l = blockIdx.x >> 8;
    int i = blockIdx.x & 255;
    int j = threadIdx.x;
    __shared__ float er[256];
    er[j] = ew2[i * 256 + j];
    __syncthreads();
    const float* lw = lin_w + l * 65536;
    float acc = 0.f;
#pragma unroll 8
    for (int m = 0; m < 256; m++) acc += er[m] * lw[m * 256 + j];
    g_W[l * 65536 + i * 256 + j] = acc;
}

__global__ void prep_bl(const float* __restrict__ eb2, const float* __restrict__ lin_w,
                        const float* __restrict__ lin_b) {
    int l = blockIdx.x;
    int j = threadIdx.x;
    const float* lw = lin_w + l * 65536;
    float acc = lin_b[l * 256 + j];
#pragma unroll 8
    for (int m = 0; m < 256; m++) acc += eb2[m] * lw[m * 256 + j];
    g_bl[l * 256 + j] = acc;
}

// ---------------- r = relu(edge_attr @ ew1 + eb1) ---------------------------
__global__ void r_kernel(const float* __restrict__ ea, const float* __restrict__ ew1,
                         const float* __restrict__ eb1) {
    int e0 = blockIdx.x * 32;
    int j = threadIdx.x;
    __shared__ float eas[32 * 8];
    eas[j] = ea[e0 * 8 + j];
    float w[8];
#pragma unroll
    for (int k = 0; k < 8; k++) w[k] = ew1[k * 256 + j];
    float b = eb1[j];
    __syncthreads();
    for (int e = 0; e < 32; e++) {
        float acc = b;
#pragma unroll
        for (int k = 0; k < 8; k++) acc += eas[e * 8 + k] * w[k];
        g_R[(e0 + e) * 256 + j] = fmaxf(acc, 0.f);
    }
}

// ---------------- h = silu([x|c] @ in_w + in_b) -----------------------------
__global__ void input_proj(const float* __restrict__ x, const float* __restrict__ c,
                           const int* __restrict__ gid, const int* __restrict__ lid,
                           const float* __restrict__ inw, const float* __restrict__ inb) {
    int n0 = blockIdx.x * 8;
    int j = threadIdx.x;
    __shared__ float xs[8 * 16];
    __shared__ float cs[8];
    if (j < 128) xs[j] = x[n0 * 16 + j];
    if (j < 8) { int n = n0 + j; cs[j] = c[gid[n] * PG + lid[n]]; }
    float w[17];
#pragma unroll
    for (int k = 0; k < 17; k++) w[k] = inw[k * 256 + j];
    float b = inb[j];
    __syncthreads();
    for (int n = 0; n < 8; n++) {
        float acc = b + cs[n] * w[16];
#pragma unroll
        for (int k = 0; k < 16; k++) acc += xs[n * 16 + k] * w[k];
        g_h[(n0 + n) * 256 + j] = siluf(acc);
    }
}

// ---------------- z = h (so scatter adds produce z = h + agg) ---------------
__global__ void copy_hz() {
    int i = blockIdx.x * blockDim.x + threadIdx.x;
    ((float4*)g_z)[i] = ((const float4*)g_h)[i];
}

// ---------------- edge GEMM + fused relu-message scatter --------------------
// msg = relu(h[src] + r@W_l + b_l); z[dst] += msg  (atomic)
__global__ void __launch_bounds__(256) edge_gemm(int l, const int* __restrict__ eidx) {
    const float* A = g_R;
    const float* Bm = g_W + l * 65536;
    const float* bias = g_bl + l * 256;
    const int* src = eidx;
    const int* dst = eidx + EE;

    __shared__ __align__(16) float As[16][64];
    __shared__ __align__(16) float Bs[16][64];
    int tid = threadIdx.x;
    int trow = tid >> 4, tcol = tid & 15;
    int row0 = blockIdx.x * 64, col0 = blockIdx.y * 64;

    float acc[16];
#pragma unroll
    for (int i = 0; i < 16; i++) acc[i] = 0.f;

    int ar = tid >> 2, ak = (tid & 3) << 2;
    int bk = tid >> 4, bc = (tid & 15) << 2;
    const float* Ap = A + (size_t)(row0 + ar) * 256 + ak;
    const float* Bp = Bm + bk * 256 + col0 + bc;

    for (int k0 = 0; k0 < 256; k0 += 16) {
        float4 av = *(const float4*)(Ap + k0);
        float4 bv = *(const float4*)(Bp + k0 * 256);
        __syncthreads();
        As[ak + 0][ar] = av.x; As[ak + 1][ar] = av.y;
        As[ak + 2][ar] = av.z; As[ak + 3][ar] = av.w;
        *(float4*)&Bs[bk][bc] = bv;
        __syncthreads();
#pragma unroll
        for (int kk = 0; kk < 16; kk++) {
            float4 a = *(const float4*)&As[kk][trow * 4];
            float4 b = *(const float4*)&Bs[kk][tcol * 4];
            acc[0]  += a.x * b.x; acc[1]  += a.x * b.y; acc[2]  += a.x * b.z; acc[3]  += a.x * b.w;
            acc[4]  += a.y * b.x; acc[5]  += a.y * b.y; acc[6]  += a.y * b.z; acc[7]  += a.y * b.w;
            acc[8]  += a.z * b.x; acc[9]  += a.z * b.y; acc[10] += a.z * b.z; acc[11] += a.z * b.w;
            acc[12] += a.w * b.x; acc[13] += a.w * b.y; acc[14] += a.w * b.z; acc[15] += a.w * b.w;
        }
    }

    int jc = col0 + tcol * 4;
    float4 bb = *(const float4*)(bias + jc);
#pragma unroll
    for (int i = 0; i < 4; i++) {
        int e = row0 + trow * 4 + i;
        int s = src[e], d = dst[e];
        float4 hv = *(const float4*)(g_h + (size_t)s * 256 + jc);
        float m0 = fmaxf(acc[i * 4 + 0] + bb.x + hv.x, 0.f);
        float m1 = fmaxf(acc[i * 4 + 1] + bb.y + hv.y, 0.f);
        float m2 = fmaxf(acc[i * 4 + 2] + bb.z + hv.z, 0.f);
        float m3 = fmaxf(acc[i * 4 + 3] + bb.w + hv.w, 0.f);
        float* zp = g_z + (size_t)d * 256 + jc;
        atomicAdd(zp + 0, m0);
        atomicAdd(zp + 1, m1);
        atomicAdd(zp + 2, m2);
        atomicAdd(zp + 3, m3);
    }
}

// ---------------- node GEMM (MODE 0: z->t with silu; MODE 1: t->hn plain) ---
template <int MODE>
__global__ void __launch_bounds__(256) node_gemm(const float* __restrict__ Bm,
                                                 const float* __restrict__ bias) {
    const float* A = (MODE == 0) ? g_z : g_t;
    float* out = (MODE == 0) ? g_t : g_hn;

    __shared__ __align__(16) float As[16][64];
    __shared__ __align__(16) float Bs[16][64];
    int tid = threadIdx.x;
    int trow = tid >> 4, tcol = tid & 15;
    int row0 = blockIdx.x * 64, col0 = blockIdx.y * 64;

    float acc[16];
#pragma unroll
    for (int i = 0; i < 16; i++) acc[i] = 0.f;

    int ar = tid >> 2, ak = (tid & 3) << 2;
    int bk = tid >> 4, bc = (tid & 15) << 2;
    int arow = row0 + ar; if (arow >= NN) arow = NN - 1;
    const float* Ap = A + (size_t)arow * 256 + ak;
    const float* Bp = Bm + bk * 256 + col0 + bc;

    for (int k0 = 0; k0 < 256; k0 += 16) {
        float4 av = *(const float4*)(Ap + k0);
        float4 bv = *(const float4*)(Bp + k0 * 256);
        __syncthreads();
        As[ak + 0][ar] = av.x; As[ak + 1][ar] = av.y;
        As[ak + 2][ar] = av.z; As[ak + 3][ar] = av.w;
        *(float4*)&Bs[bk][bc] = bv;
        __syncthreads();
#pragma unroll
        for (int kk = 0; kk < 16; kk++) {
            float4 a = *(const float4*)&As[kk][trow * 4];
            float4 b = *(const float4*)&Bs[kk][tcol * 4];
            acc[0]  += a.x * b.x; acc[1]  += a.x * b.y; acc[2]  += a.x * b.z; acc[3]  += a.x * b.w;
            acc[4]  += a.y * b.x; acc[5]  += a.y * b.y; acc[6]  += a.y * b.z; acc[7]  += a.y * b.w;
            acc[8]  += a.z * b.x; acc[9]  += a.z * b.y; acc[10] += a.z * b.z; acc[11] += a.z * b.w;
            acc[12] += a.w * b.x; acc[13] += a.w * b.y; acc[14] += a.w * b.z; acc[15] += a.w * b.w;
        }
    }

    int jc = col0 + tcol * 4;
    float4 bb = *(const float4*)(bias + jc);
#pragma unroll
    for (int i = 0; i < 4; i++) {
        int r = row0 + trow * 4 + i;
        if (r < NN) {
            float4 o;
            o.x = acc[i * 4 + 0] + bb.x;
            o.y = acc[i * 4 + 1] + bb.y;
            o.z = acc[i * 4 + 2] + bb.z;
            o.w = acc[i * 4 + 3] + bb.w;
            if (MODE == 0) { o.x = siluf(o.x); o.y = siluf(o.y); o.z = siluf(o.z); o.w = siluf(o.w); }
            *(float4*)(out + (size_t)r * 256 + jc) = o;
        }
    }
}

// ---------------- LayerNorm + residual silu update --------------------------
__global__ void ln_update(int l, const float* __restrict__ lng, const float* __restrict__ lnb) {
    int warp = threadIdx.x >> 5, lane = threadIdx.x & 31;
    int n = blockIdx.x * 8 + warp;
    const float* g = lng + l * 256;
    const float* b = lnb + l * 256;
    const float* row = g_hn + (size_t)n * 256;
    float v[8];
    float s = 0.f, ss = 0.f;
#pragma unroll
    for (int t = 0; t < 8; t++) {
        v[t] = row[lane + 32 * t];
        s += v[t]; ss += v[t] * v[t];
    }
#pragma unroll
    for (int o = 16; o > 0; o >>= 1) {
        s += __shfl_xor_sync(~0u, s, o);
        ss += __shfl_xor_sync(~0u, ss, o);
    }
    float m = s * (1.f / 256.f);
    float var = ss * (1.f / 256.f) - m * m;
    float r = rsqrtf(var + 1e-5f);
    float* hrow = g_h + (size_t)n * 256;
#pragma unroll
    for (int t = 0; t < 8; t++) {
        int cidx = lane + 32 * t;
        float u = (v[t] - m) * r * g[cidx] + b[cidx];
        hrow[cidx] += siluf(u);
    }
}

// ---------------- attention scores: tanh(h@paw1+b1)@paw2+b2 ----------------
__global__ void __launch_bounds__(256) scores_kernel(const float* __restrict__ w1,
                                                     const float* __restrict__ b1,
                                                     const float* __restrict__ w2,
                                                     const float* __restrict__ b2) {
    int n0 = blockIdx.x * 32;
    int j = threadIdx.x;
    __shared__ float hs[32][256];
    __shared__ float part[32][8];
    for (int i = j; i < 32 * 256; i += 256) hs[i >> 8][i & 255] = g_h[(size_t)n0 * 256 + i];
    float acc[32];
#pragma unroll
    for (int n = 0; n < 32; n++) acc[n] = 0.f;
    __syncthreads();
    for (int k = 0; k < 256; k++) {
        float w = w1[k * 256 + j];
#pragma unroll
        for (int n = 0; n < 32; n++) acc[n] += hs[n][k] * w;
    }
    float b1j = b1[j], w2j = w2[j];
    int lane = j & 31, wid = j >> 5;
#pragma unroll
    for (int n = 0; n < 32; n++) {
        float val = tanhf(acc[n] + b1j) * w2j;
#pragma unroll
        for (int o = 16; o > 0; o >>= 1) val += __shfl_xor_sync(~0u, val, o);
        if (lane == 0) part[n][wid] = val;
    }
    __syncthreads();
    if (j < 32) {
        float sres = b2[0];
#pragma unroll
        for (int w = 0; w < 8; w++) sres += part[j][w];
        g_scores[n0 + j] = sres;
    }
}

// ---------------- global softmax stats --------------------------------------
__global__ void softmax_stats() {
    __shared__ float red[1024];
    int t = threadIdx.x;
    float m = -1e30f;
    for (int i = t; i < NN; i += 1024) m = fmaxf(m, g_scores[i]);
    red[t] = m;
    __syncthreads();
    for (int o = 512; o > 0; o >>= 1) {
        if (t < o) red[t] = fmaxf(red[t], red[t + o]);
        __syncthreads();
    }
    float gmax = red[0];
    __syncthreads();
    float s = 0.f;
    for (int i = t; i < NN; i += 1024) s += expf(g_scores[i] - gmax);
    red[t] = s;
    __syncthreads();
    for (int o = 512; o > 0; o >>= 1) {
        if (t < o) red[t] += red[t + o];
        __syncthreads();
    }
    if (t == 0) { g_stats[0] = gmax; g_stats[1] = red[0]; }
}

// ---------------- per-graph renormalized attention weights ------------------
__global__ void seg_attn() {
    int g = blockIdx.x, t = threadIdx.x;
    float gmax = g_stats[0], Z = g_stats[1];
    int base = g * PG;
    float s = 0.f;
    for (int i = t; i < PG; i += 256) s += expf(g_scores[base + i] - gmax);
    __shared__ float red[256];
    red[t] = s;
    __syncthreads();
    for (int o = 128; o > 0; o >>= 1) {
        if (t < o) red[t] += red[t + o];
        __syncthreads();
    }
    float denom = red[0] / Z + 1e-8f;
    float scale = 1.f / (Z * denom);
    for (int i = t; i < PG; i += 256) g_attn[base + i] = expf(g_scores[base + i] - gmax) * scale;
    g_pooled[g * 256 + t] = 0.f;
}

// ---------------- weighted pooling ------------------------------------------
__global__ void pool_kernel() {
    int g = blockIdx.x, chunk = blockIdx.y, j = threadIdx.x;
    int base = g * PG + chunk * 250;
    float acc = 0.f;
    for (int i = 0; i < 250; i++)
        acc += g_h[(size_t)(base + i) * 256 + j] * g_attn[base + i];
    atomicAdd(&g_pooled[g * 256 + j], acc);
}

// ---------------- head -------------------------------------------------------
__global__ void head_kernel(const float* __restrict__ hw1, const float* __restrict__ hb1,
                            const float* __restrict__ hw2, const float* __restrict__ hb2,
                            float* __restrict__ out) {
    int g = blockIdx.x, j = threadIdx.x;
    __shared__ float ps[256];
    __shared__ float red[256];
    ps[j] = g_pooled[g * 256 + j];
    __syncthreads();
    float acc = hb1[j];
#pragma unroll 8
    for (int k = 0; k < 256; k++) acc += ps[k] * hw1[k * 256 + j];
    red[j] = siluf(acc) * hw2[j];
    __syncthreads();
    for (int o = 128; o > 0; o >>= 1) {
        if (j < o) red[j] += red[j + o];
        __syncthreads();
    }
    if (j == 0) out[g] = red[0] + hb2[0];
}

// ---------------- launch -----------------------------------------------------
extern "C" void kernel_launch(void* const* d_in, const int* in_sizes, int n_in,
                              void* d_out, int out_size) {
    const float* x    = (const float*)d_in[0];
    const float* ea   = (const float*)d_in[1];
    const float* c    = (const float*)d_in[2];
    const int*   eidx = (const int*)  d_in[3];
    const int*   gid  = (const int*)  d_in[4];
    const int*   lid  = (const int*)  d_in[5];
    const float* ew1  = (const float*)d_in[6];
    const float* eb1  = (const float*)d_in[7];
    const float* ew2  = (const float*)d_in[8];
    const float* eb2  = (const float*)d_in[9];
    const float* inw  = (const float*)d_in[10];
    const float* inb  = (const float*)d_in[11];
    const float* lin_w = (const float*)d_in[12];
    const float* lin_b = (const float*)d_in[13];
    const float* cw1  = (const float*)d_in[14];
    const float* cb1  = (const float*)d_in[15];
    const float* cw2  = (const float*)d_in[16];
    const float* cb2  = (const float*)d_in[17];
    const float* lng  = (const float*)d_in[18];
    const float* lnb  = (const float*)d_in[19];
    const float* paw1 = (const float*)d_in[20];
    const float* pab1 = (const float*)d_in[21];
    const float* paw2 = (const float*)d_in[22];
    const float* pab2 = (const float*)d_in[23];
    const float* hw1  = (const float*)d_in[24];
    const float* hb1  = (const float*)d_in[25];
    const float* hw2  = (const float*)d_in[26];
    const float* hb2  = (const float*)d_in[27];
    float* out = (float*)d_out;

    prep_W<<<LL * 256, 256>>>(ew2, lin_w);
    prep_bl<<<LL, 256>>>(eb2, lin_w, lin_b);
    r_kernel<<<EE / 32, 256>>>(ea, ew1, eb1);
    input_proj<<<NN / 8, 256>>>(x, c, gid, lid, inw, inb);

    for (int l = 0; l < LL; l++) {
        copy_hz<<<(NN * HH / 4) / 256, 256>>>();
        edge_gemm<<<dim3(EE / 64, 4), 256>>>(l, eidx);
        node_gemm<0><<<dim3((NN + 63) / 64, 4), 256>>>(cw1 + l * 65536, cb1 + l * 256);
        node_gemm<1><<<dim3((NN + 63) / 64, 4), 256>>>(cw2 + l * 65536, cb2 + l * 256);
        ln_update<<<NN / 8, 256>>>(l, lng, lnb);
    }

    scores_kernel<<<NN / 32, 256>>>(paw1, pab1, paw2, pab2);
    softmax_stats<<<1, 1024>>>();
    seg_attn<<<GB, 256>>>();
    pool_kernel<<<dim3(GB, 4), 256>>>();
    head_kernel<<<GB, 256>>>(hw1, hb1, hw2, hb2, out);
    (void)in_sizes; (void)n_in; (void)out_size;
}

// round 3
// speedup vs baseline: 1.9584x; 1.9584x over previous
#include <cuda_runtime.h>
#include <cuda_bf16.h>
#include <math.h>
#include <stdint.h>

#define NN 20000
#define EE 320000
#define HH 256
#define LL 6
#define GB 20
#define PG 1000

// ---------------- scratch ----------------------------------------------------
__device__ __nv_bfloat16 g_Rhi[(size_t)EE * HH];
__device__ __nv_bfloat16 g_Rlo[(size_t)EE * HH];
__device__ __nv_bfloat16 g_WThi[LL * HH * HH];   // folded weights, transposed [l][n][k]
__device__ __nv_bfloat16 g_WTlo[LL * HH * HH];
__device__ float g_bl[LL * HH];
__device__ float g_h[NN * HH];
__device__ float g_z[NN * HH];
__device__ float g_t[NN * HH];
__device__ float g_hn[NN * HH];
__device__ float g_scores[NN];
__device__ float g_attn[NN];
__device__ float g_stats[2];
__device__ float g_pooled[GB * HH];

__device__ __forceinline__ float siluf(float x) { return x / (1.f + expf(-x)); }

__device__ __forceinline__ uint32_t smem_u32(const void* p) {
    uint32_t a;
    asm("{ .reg .u64 t; cvta.to.shared.u64 t, %1; cvt.u32.u64 %0, t; }" : "=r"(a) : "l"(p));
    return a;
}
__device__ __forceinline__ uint32_t swz(uint32_t o) { return o ^ ((o >> 3) & 0x70); }

#define LDSM4(r, addr) \
    asm volatile("ldmatrix.sync.aligned.m8n8.x4.shared.b16 {%0,%1,%2,%3}, [%4];" \
        : "=r"((r)[0]), "=r"((r)[1]), "=r"((r)[2]), "=r"((r)[3]) : "r"(addr))

__device__ __forceinline__ void mma16816(float* d, const uint32_t* a, uint32_t b0, uint32_t b1) {
    asm volatile("mma.sync.aligned.m16n8k16.row.col.f32.bf16.bf16.f32 "
        "{%0,%1,%2,%3}, {%4,%5,%6,%7}, {%8,%9}, {%0,%1,%2,%3};"
        : "+f"(d[0]), "+f"(d[1]), "+f"(d[2]), "+f"(d[3])
        : "r"(a[0]), "r"(a[1]), "r"(a[2]), "r"(a[3]), "r"(b0), "r"(b1));
}

// ---------------- weight folding: WT_l = (ew2 @ lin_w[l])^T, split bf16 -----
__global__ void prep_W(const float* __restrict__ ew2, const float* __restrict__ lin_w) {
    int l = blockIdx.x >> 8;
    int i = blockIdx.x & 255;   // K index
    int j = threadIdx.x;        // N index
    __shared__ float er[256];
    er[j] = ew2[i * 256 + j];
    __syncthreads();
    const float* lw = lin_w + l * 65536;
    float acc = 0.f;
#pragma unroll 8
    for (int m = 0; m < 256; m++) acc += er[m] * lw[m * 256 + j];
    __nv_bfloat16 hi = __float2bfloat16(acc);
    g_WThi[l * 65536 + j * 256 + i] = hi;
    g_WTlo[l * 65536 + j * 256 + i] = __float2bfloat16(acc - __bfloat162float(hi));
}

__global__ void prep_bl(const float* __restrict__ eb2, const float* __restrict__ lin_w,
                        const float* __restrict__ lin_b) {
    int l = blockIdx.x;
    int j = threadIdx.x;
    const float* lw = lin_w + l * 65536;
    float acc = lin_b[l * 256 + j];
#pragma unroll 8
    for (int m = 0; m < 256; m++) acc += eb2[m] * lw[m * 256 + j];
    g_bl[l * 256 + j] = acc;
}

// ---------------- r = relu(edge_attr @ ew1 + eb1), split bf16 hi/lo ---------
__global__ void r_kernel(const float* __restrict__ ea, const float* __restrict__ ew1,
                         const float* __restrict__ eb1) {
    int e0 = blockIdx.x * 32;
    int j = threadIdx.x;
    __shared__ float eas[32 * 8];
    eas[j] = ea[e0 * 8 + j];
    float w[8];
#pragma unroll
    for (int k = 0; k < 8; k++) w[k] = ew1[k * 256 + j];
    float b = eb1[j];
    __syncthreads();
    for (int e = 0; e < 32; e++) {
        float acc = b;
#pragma unroll
        for (int k = 0; k < 8; k++) acc += eas[e * 8 + k] * w[k];
        float v = fmaxf(acc, 0.f);
        __nv_bfloat16 hi = __float2bfloat16(v);
        size_t idx = (size_t)(e0 + e) * 256 + j;
        g_Rhi[idx] = hi;
        g_Rlo[idx] = __float2bfloat16(v - __bfloat162float(hi));
    }
}

// ---------------- h = silu([x|c] @ in_w + in_b) -----------------------------
__global__ void input_proj(const float* __restrict__ x, const float* __restrict__ c,
                           const int* __restrict__ gid, const int* __restrict__ lid,
                           const float* __restrict__ inw, const float* __restrict__ inb) {
    int n0 = blockIdx.x * 8;
    int j = threadIdx.x;
    __shared__ float xs[8 * 16];
    __shared__ float cs[8];
    if (j < 128) xs[j] = x[n0 * 16 + j];
    if (j < 8) { int n = n0 + j; cs[j] = c[gid[n] * PG + lid[n]]; }
    float w[17];
#pragma unroll
    for (int k = 0; k < 17; k++) w[k] = inw[k * 256 + j];
    float b = inb[j];
    __syncthreads();
    for (int n = 0; n < 8; n++) {
        float acc = b + cs[n] * w[16];
#pragma unroll
        for (int k = 0; k < 16; k++) acc += xs[n * 16 + k] * w[k];
        g_h[(n0 + n) * 256 + j] = siluf(acc);
    }
}

// ---------------- z = h ------------------------------------------------------
__global__ void copy_hz() {
    int i = blockIdx.x * blockDim.x + threadIdx.x;
    ((float4*)g_z)[i] = ((const float4*)g_h)[i];
}

// ---------------- bf16x3 mma.sync edge GEMM + fused relu-message scatter ----
// CTA: 128 edges x 128 cols. 8 warps (4m x 2n), warp tile 32x64.
// D = Rhi@Whi + Rhi@Wlo + Rlo@Whi (fp32 acc); msg = relu(D + b + h[src]); z[dst] += msg
#define EDGE_SMEM_MMA (65536 + 512)

__global__ void __launch_bounds__(256, 2) edge_mma(int l, const int* __restrict__ eidx) {
    extern __shared__ char sm[];
    uint32_t sbase = smem_u32(sm);
    // [0,16K) Ahi  [16K,32K) Alo  [32K,48K) Bhi  [48K,64K) Blo  [64K,+512) bias
    float* sBias = (float*)(sm + 65536);

    int tid = threadIdx.x, lane = tid & 31, wid = tid >> 5;
    int wm = wid & 3, wn = wid >> 2;
    int row0 = blockIdx.x * 128, col0 = blockIdx.y * 128;

    if (tid < 128) sBias[tid] = g_bl[l * 256 + col0 + tid];

    float acc[16][4];
#pragma unroll
    for (int i = 0; i < 16; i++) {
        acc[i][0] = 0.f; acc[i][1] = 0.f; acc[i][2] = 0.f; acc[i][3] = 0.f;
    }

    const uint4* Ah = (const uint4*)g_Rhi + (size_t)row0 * 32;
    const uint4* Al = (const uint4*)g_Rlo + (size_t)row0 * 32;
    const uint4* Bh = (const uint4*)g_WThi + (size_t)l * 8192 + (size_t)col0 * 32;
    const uint4* Bl = (const uint4*)g_WTlo + (size_t)l * 8192 + (size_t)col0 * 32;

    for (int c = 0; c < 4; c++) {
        __syncthreads();
#pragma unroll
        for (int i = 0; i < 4; i++) {
            int elem = tid + 256 * i;        // 0..1023
            int r = elem >> 3, u = elem & 7;
            uint32_t so = swz((uint32_t)(r * 128 + u * 16));
            size_t gi = (size_t)r * 32 + c * 8 + u;
            *(uint4*)(sm + so)         = Ah[gi];
            *(uint4*)(sm + 16384 + so) = Al[gi];
            *(uint4*)(sm + 32768 + so) = Bh[gi];
            *(uint4*)(sm + 49152 + so) = Bl[gi];
        }
        __syncthreads();

#pragma unroll
        for (int ks = 0; ks < 4; ks++) {
            uint32_t ahi[2][4], alo[2][4];
#pragma unroll
            for (int mt = 0; mt < 2; mt++) {
                int row = wm * 32 + mt * 16 + (lane & 15);
                int kb = ks * 32 + ((lane >> 4) << 4);
                uint32_t ad = sbase + swz((uint32_t)(row * 128 + kb));
                LDSM4(ahi[mt], ad);
                LDSM4(alo[mt], ad + 16384);
            }
#pragma unroll
            for (int np = 0; np < 4; np++) {
                int g = lane >> 3, li = lane & 7;
                int brow = wn * 64 + np * 16 + ((g >> 1) << 3) + li;
                int bkb = ks * 32 + ((g & 1) << 4);
                uint32_t bd = sbase + 32768 + swz((uint32_t)(brow * 128 + bkb));
                uint32_t bh[4], bl[4];
                LDSM4(bh, bd);
                LDSM4(bl, bd + 16384);
#pragma unroll
                for (int t = 0; t < 2; t++) {
#pragma unroll
                    for (int mt = 0; mt < 2; mt++) {
                        float* d = acc[mt * 8 + np * 2 + t];
                        mma16816(d, ahi[mt], bh[2 * t], bh[2 * t + 1]);
                        mma16816(d, ahi[mt], bl[2 * t], bl[2 * t + 1]);
                        mma16816(d, alo[mt], bh[2 * t], bh[2 * t + 1]);
                    }
                }
            }
        }
    }

    // ------- epilogue: relu(acc + bias + h[src]) -> red to z[dst] -------
    int q = lane >> 2;
    int c2 = (lane & 3) * 2;
    int src_[2][2], dst_[2][2];
#pragma unroll
    for (int mt = 0; mt < 2; mt++)
#pragma unroll
        for (int h = 0; h < 2; h++) {
            int e = row0 + wm * 32 + mt * 16 + h * 8 + q;
            src_[mt][h] = eidx[e];
            dst_[mt][h] = eidx[EE + e];
        }

#pragma unroll
    for (int mt = 0; mt < 2; mt++) {
#pragma unroll
        for (int nt = 0; nt < 8; nt++) {
            float* a = acc[mt * 8 + nt];
            int coln = wn * 64 + nt * 8 + c2;
            int col = col0 + coln;
            float2 bb = *(float2*)(sBias + coln);
#pragma unroll
            for (int h = 0; h < 2; h++) {
                const float2 hv = *(const float2*)(g_h + (size_t)src_[mt][h] * 256 + col);
                float v0 = fmaxf(a[2 * h + 0] + bb.x + hv.x, 0.f);
                float v1 = fmaxf(a[2 * h + 1] + bb.y + hv.y, 0.f);
                float* zp = g_z + (size_t)dst_[mt][h] * 256 + col;
                asm volatile("red.global.add.v2.f32 [%0], {%1,%2};"
                             :: "l"(zp), "f"(v0), "f"(v1) : "memory");
            }
        }
    }
}

// ---------------- node GEMM (MODE 0: z->t with silu; MODE 1: t->hn plain) ---
template <int MODE>
__global__ void __launch_bounds__(256) node_gemm(const float* __restrict__ Bm,
                                                 const float* __restrict__ bias) {
    const float* A = (MODE == 0) ? g_z : g_t;
    float* out = (MODE == 0) ? g_t : g_hn;

    __shared__ __align__(16) float As[16][64];
    __shared__ __align__(16) float Bs[16][64];
    int tid = threadIdx.x;
    int trow = tid >> 4, tcol = tid & 15;
    int row0 = blockIdx.x * 64, col0 = blockIdx.y * 64;

    float acc[16];
#pragma unroll
    for (int i = 0; i < 16; i++) acc[i] = 0.f;

    int ar = tid >> 2, ak = (tid & 3) << 2;
    int bk = tid >> 4, bc = (tid & 15) << 2;
    int arow = row0 + ar; if (arow >= NN) arow = NN - 1;
    const float* Ap = A + (size_t)arow * 256 + ak;
    const float* Bp = Bm + bk * 256 + col0 + bc;

    for (int k0 = 0; k0 < 256; k0 += 16) {
        float4 av = *(const float4*)(Ap + k0);
        float4 bv = *(const float4*)(Bp + k0 * 256);
        __syncthreads();
        As[ak + 0][ar] = av.x; As[ak + 1][ar] = av.y;
        As[ak + 2][ar] = av.z; As[ak + 3][ar] = av.w;
        *(float4*)&Bs[bk][bc] = bv;
        __syncthreads();
#pragma unroll
        for (int kk = 0; kk < 16; kk++) {
            float4 a = *(const float4*)&As[kk][trow * 4];
            float4 b = *(const float4*)&Bs[kk][tcol * 4];
            acc[0]  += a.x * b.x; acc[1]  += a.x * b.y; acc[2]  += a.x * b.z; acc[3]  += a.x * b.w;
            acc[4]  += a.y * b.x; acc[5]  += a.y * b.y; acc[6]  += a.y * b.z; acc[7]  += a.y * b.w;
            acc[8]  += a.z * b.x; acc[9]  += a.z * b.y; acc[10] += a.z * b.z; acc[11] += a.z * b.w;
            acc[12] += a.w * b.x; acc[13] += a.w * b.y; acc[14] += a.w * b.z; acc[15] += a.w * b.w;
        }
    }

    int jc = col0 + tcol * 4;
    float4 bb = *(const float4*)(bias + jc);
#pragma unroll
    for (int i = 0; i < 4; i++) {
        int r = row0 + trow * 4 + i;
        if (r < NN) {
            float4 o;
            o.x = acc[i * 4 + 0] + bb.x;
            o.y = acc[i * 4 + 1] + bb.y;
            o.z = acc[i * 4 + 2] + bb.z;
            o.w = acc[i * 4 + 3] + bb.w;
            if (MODE == 0) { o.x = siluf(o.x); o.y = siluf(o.y); o.z = siluf(o.z); o.w = siluf(o.w); }
            *(float4*)(out + (size_t)r * 256 + jc) = o;
        }
    }
}

// ---------------- LayerNorm + residual silu update --------------------------
__global__ void ln_update(int l, const float* __restrict__ lng, const float* __restrict__ lnb) {
    int warp = threadIdx.x >> 5, lane = threadIdx.x & 31;
    int n = blockIdx.x * 8 + warp;
    const float* g = lng + l * 256;
    const float* b = lnb + l * 256;
    const float* row = g_hn + (size_t)n * 256;
    float v[8];
    float s = 0.f, ss = 0.f;
#pragma unroll
    for (int t = 0; t < 8; t++) {
        v[t] = row[lane + 32 * t];
        s += v[t]; ss += v[t] * v[t];
    }
#pragma unroll
    for (int o = 16; o > 0; o >>= 1) {
        s += __shfl_xor_sync(~0u, s, o);
        ss += __shfl_xor_sync(~0u, ss, o);
    }
    float m = s * (1.f / 256.f);
    float var = ss * (1.f / 256.f) - m * m;
    float r = rsqrtf(var + 1e-5f);
    float* hrow = g_h + (size_t)n * 256;
#pragma unroll
    for (int t = 0; t < 8; t++) {
        int cidx = lane + 32 * t;
        float u = (v[t] - m) * r * g[cidx] + b[cidx];
        hrow[cidx] += siluf(u);
    }
}

// ---------------- attention scores ------------------------------------------
__global__ void __launch_bounds__(256) scores_kernel(const float* __restrict__ w1,
                                                     const float* __restrict__ b1,
                                                     const float* __restrict__ w2,
                                                     const float* __restrict__ b2) {
    int n0 = blockIdx.x * 32;
    int j = threadIdx.x;
    __shared__ float hs[32][256];
    __shared__ float part[32][8];
    for (int i = j; i < 32 * 256; i += 256) hs[i >> 8][i & 255] = g_h[(size_t)n0 * 256 + i];
    float acc[32];
#pragma unroll
    for (int n = 0; n < 32; n++) acc[n] = 0.f;
    __syncthreads();
    for (int k = 0; k < 256; k++) {
        float w = w1[k * 256 + j];
#pragma unroll
        for (int n = 0; n < 32; n++) acc[n] += hs[n][k] * w;
    }
    float b1j = b1[j], w2j = w2[j];
    int lane = j & 31, wid = j >> 5;
#pragma unroll
    for (int n = 0; n < 32; n++) {
        float val = tanhf(acc[n] + b1j) * w2j;
#pragma unroll
        for (int o = 16; o > 0; o >>= 1) val += __shfl_xor_sync(~0u, val, o);
        if (lane == 0) part[n][wid] = val;
    }
    __syncthreads();
    if (j < 32) {
        float sres = b2[0];
#pragma unroll
        for (int w = 0; w < 8; w++) sres += part[j][w];
        g_scores[n0 + j] = sres;
    }
}

// ---------------- global softmax stats --------------------------------------
__global__ void softmax_stats() {
    __shared__ float red[1024];
    int t = threadIdx.x;
    float m = -1e30f;
    for (int i = t; i < NN; i += 1024) m = fmaxf(m, g_scores[i]);
    red[t] = m;
    __syncthreads();
    for (int o = 512; o > 0; o >>= 1) {
        if (t < o) red[t] = fmaxf(red[t], red[t + o]);
        __syncthreads();
    }
    float gmax = red[0];
    __syncthreads();
    float s = 0.f;
    for (int i = t; i < NN; i += 1024) s += expf(g_scores[i] - gmax);
    red[t] = s;
    __syncthreads();
    for (int o = 512; o > 0; o >>= 1) {
        if (t < o) red[t] += red[t + o];
        __syncthreads();
    }
    if (t == 0) { g_stats[0] = gmax; g_stats[1] = red[0]; }
}

// ---------------- per-graph renormalized attention --------------------------
__global__ void seg_attn() {
    int g = blockIdx.x, t = threadIdx.x;
    float gmax = g_stats[0], Z = g_stats[1];
    int base = g * PG;
    float s = 0.f;
    for (int i = t; i < PG; i += 256) s += expf(g_scores[base + i] - gmax);
    __shared__ float red[256];
    red[t] = s;
    __syncthreads();
    for (int o = 128; o > 0; o >>= 1) {
        if (t < o) red[t] += red[t + o];
        __syncthreads();
    }
    float denom = red[0] / Z + 1e-8f;
    float scale = 1.f / (Z * denom);
    for (int i = t; i < PG; i += 256) g_attn[base + i] = expf(g_scores[base + i] - gmax) * scale;
    g_pooled[g * 256 + t] = 0.f;
}

// ---------------- weighted pooling ------------------------------------------
__global__ void pool_kernel() {
    int g = blockIdx.x, chunk = blockIdx.y, j = threadIdx.x;
    int base = g * PG + chunk * 250;
    float acc = 0.f;
    for (int i = 0; i < 250; i++)
        acc += g_h[(size_t)(base + i) * 256 + j] * g_attn[base + i];
    atomicAdd(&g_pooled[g * 256 + j], acc);
}

// ---------------- head -------------------------------------------------------
__global__ void head_kernel(const float* __restrict__ hw1, const float* __restrict__ hb1,
                            const float* __restrict__ hw2, const float* __restrict__ hb2,
                            float* __restrict__ out) {
    int g = blockIdx.x, j = threadIdx.x;
    __shared__ float ps[256];
    __shared__ float red[256];
    ps[j] = g_pooled[g * 256 + j];
    __syncthreads();
    float acc = hb1[j];
#pragma unroll 8
    for (int k = 0; k < 256; k++) acc += ps[k] * hw1[k * 256 + j];
    red[j] = siluf(acc) * hw2[j];
    __syncthreads();
    for (int o = 128; o > 0; o >>= 1) {
        if (j < o) red[j] += red[j + o];
        __syncthreads();
    }
    if (j == 0) out[g] = red[0] + hb2[0];
}

// ---------------- launch -----------------------------------------------------
extern "C" void kernel_launch(void* const* d_in, const int* in_sizes, int n_in,
                              void* d_out, int out_size) {
    const float* x    = (const float*)d_in[0];
    const float* ea   = (const float*)d_in[1];
    const float* c    = (const float*)d_in[2];
    const int*   eidx = (const int*)  d_in[3];
    const int*   gid  = (const int*)  d_in[4];
    const int*   lid  = (const int*)  d_in[5];
    const float* ew1  = (const float*)d_in[6];
    const float* eb1  = (const float*)d_in[7];
    const float* ew2  = (const float*)d_in[8];
    const float* eb2  = (const float*)d_in[9];
    const float* inw  = (const float*)d_in[10];
    const float* inb  = (const float*)d_in[11];
    const float* lin_w = (const float*)d_in[12];
    const float* lin_b = (const float*)d_in[13];
    const float* cw1  = (const float*)d_in[14];
    const float* cb1  = (const float*)d_in[15];
    const float* cw2  = (const float*)d_in[16];
    const float* cb2  = (const float*)d_in[17];
    const float* lng  = (const float*)d_in[18];
    const float* lnb  = (const float*)d_in[19];
    const float* paw1 = (const float*)d_in[20];
    const float* pab1 = (const float*)d_in[21];
    const float* paw2 = (const float*)d_in[22];
    const float* pab2 = (const float*)d_in[23];
    const float* hw1  = (const float*)d_in[24];
    const float* hb1  = (const float*)d_in[25];
    const float* hw2  = (const float*)d_in[26];
    const float* hb2  = (const float*)d_in[27];
    float* out = (float*)d_out;

    static int attr_done = 0;
    if (!attr_done) {
        cudaFuncSetAttribute((const void*)edge_mma,
                             cudaFuncAttributeMaxDynamicSharedMemorySize, EDGE_SMEM_MMA);
        attr_done = 1;
    }

    prep_W<<<LL * 256, 256>>>(ew2, lin_w);
    prep_bl<<<LL, 256>>>(eb2, lin_w, lin_b);
    r_kernel<<<EE / 32, 256>>>(ea, ew1, eb1);
    input_proj<<<NN / 8, 256>>>(x, c, gid, lid, inw, inb);

    for (int l = 0; l < LL; l++) {
        copy_hz<<<(NN * HH / 4) / 256, 256>>>();
        edge_mma<<<dim3(EE / 128, 2), 256, EDGE_SMEM_MMA>>>(l, eidx);
        node_gemm<0><<<dim3((NN + 63) / 64, 4), 256>>>(cw1 + l * 65536, cb1 + l * 256);
        node_gemm<1><<<dim3((NN + 63) / 64, 4), 256>>>(cw2 + l * 65536, cb2 + l * 256);
        ln_update<<<NN / 8, 256>>>(l, lng, lnb);
    }

    scores_kernel<<<NN / 32, 256>>>(paw1, pab1, paw2, pab2);
    softmax_stats<<<1, 1024>>>();
    seg_attn<<<GB, 256>>>();
    pool_kernel<<<dim3(GB, 4), 256>>>();
    head_kernel<<<GB, 256>>>(hw1, hb1, hw2, hb2, out);
    (void)in_sizes; (void)n_in; (void)out_size;
}

// round 5
// speedup vs baseline: 3.7532x; 1.9164x over previous
#include <cuda_runtime.h>
#include <cuda_bf16.h>
#include <cuda_fp16.h>
#include <math.h>
#include <stdint.h>

#define NN 20000
#define EE 320000
#define HH 256
#define LL 6
#define GB 20
#define PG 1000
#define NPAD 20096   // 157*128

// ---------------- scratch ----------------------------------------------------
__device__ __half g_R16[(size_t)EE * HH];        // fp16 edge features
__device__ __half g_W16[LL * HH * HH];           // fp16 folded edge weights [l][n][k]
__device__ float g_bl[LL * HH];
__device__ float g_h[NN * HH];
__device__ float g_z[NN * HH];
__device__ float g_hn[NN * HH];
__device__ __nv_bfloat16 g_zhi[NPAD * HH], g_zlo[NPAD * HH];
__device__ __nv_bfloat16 g_thi[NPAD * HH], g_tlo[NPAD * HH];
__device__ __nv_bfloat16 g_cw1hi[LL * HH * HH], g_cw1lo[LL * HH * HH];  // [l][n][k]
__device__ __nv_bfloat16 g_cw2hi[LL * HH * HH], g_cw2lo[LL * HH * HH];
__device__ float g_scores[NN];
__device__ float g_attn[NN];
__device__ float g_stats[2];
__device__ float g_pooled[GB * HH];

__device__ __forceinline__ float siluf(float x) { return x / (1.f + expf(-x)); }

__device__ __forceinline__ uint32_t smem_u32(const void* p) {
    uint32_t a;
    asm("{ .reg .u64 t; cvta.to.shared.u64 t, %1; cvt.u32.u64 %0, t; }" : "=r"(a) : "l"(p));
    return a;
}
__device__ __forceinline__ uint32_t swz(uint32_t o) { return o ^ ((o >> 3) & 0x70); }

#define LDSM4(r, addr) \
    asm volatile("ldmatrix.sync.aligned.m8n8.x4.shared.b16 {%0,%1,%2,%3}, [%4];" \
        : "=r"((r)[0]), "=r"((r)[1]), "=r"((r)[2]), "=r"((r)[3]) : "r"(addr))

__device__ __forceinline__ void mma_bf16(float* d, const uint32_t* a, uint32_t b0, uint32_t b1) {
    asm volatile("mma.sync.aligned.m16n8k16.row.col.f32.bf16.bf16.f32 "
        "{%0,%1,%2,%3}, {%4,%5,%6,%7}, {%8,%9}, {%0,%1,%2,%3};"
        : "+f"(d[0]), "+f"(d[1]), "+f"(d[2]), "+f"(d[3])
        : "r"(a[0]), "r"(a[1]), "r"(a[2]), "r"(a[3]), "r"(b0), "r"(b1));
}
__device__ __forceinline__ void mma_f16(float* d, const uint32_t* a, uint32_t b0, uint32_t b1) {
    asm volatile("mma.sync.aligned.m16n8k16.row.col.f32.f16.f16.f32 "
        "{%0,%1,%2,%3}, {%4,%5,%6,%7}, {%8,%9}, {%0,%1,%2,%3};"
        : "+f"(d[0]), "+f"(d[1]), "+f"(d[2]), "+f"(d[3])
        : "r"(a[0]), "r"(a[1]), "r"(a[2]), "r"(a[3]), "r"(b0), "r"(b1));
}

#define CPA16(d, s) asm volatile("cp.async.cg.shared.global [%0], [%1], 16;" :: "r"(d), "l"(s) : "memory")
#define CPC        asm volatile("cp.async.commit_group;" ::: "memory")
#define CPW1       asm volatile("cp.async.wait_group 1;" ::: "memory")
#define CPW0       asm volatile("cp.async.wait_group 0;" ::: "memory")

#define PIPE_SMEM (98304 + 512)

// ---------------- weight folding: W16_l = (ew2 @ lin_w[l])^T fp16 -----------
__global__ void prep_W(const float* __restrict__ ew2, const float* __restrict__ lin_w) {
    int l = blockIdx.x >> 8;
    int i = blockIdx.x & 255;   // K index
    int j = threadIdx.x;        // N index
    __shared__ float er[256];
    er[j] = ew2[i * 256 + j];
    __syncthreads();
    const float* lw = lin_w + l * 65536;
    float acc = 0.f;
#pragma unroll 8
    for (int m = 0; m < 256; m++) acc += er[m] * lw[m * 256 + j];
    g_W16[l * 65536 + j * 256 + i] = __float2half(acc);
}

__global__ void prep_bl(const float* __restrict__ eb2, const float* __restrict__ lin_w,
                        const float* __restrict__ lin_b) {
    int l = blockIdx.x;
    int j = threadIdx.x;
    const float* lw = lin_w + l * 65536;
    float acc = lin_b[l * 256 + j];
#pragma unroll 8
    for (int m = 0; m < 256; m++) acc += eb2[m] * lw[m * 256 + j];
    g_bl[l * 256 + j] = acc;
}

// ---------------- node weight transpose + bf16 split -------------------------
__global__ void prep_nw(const float* __restrict__ cw1, const float* __restrict__ cw2) {
    int n = blockIdx.x, l = blockIdx.y, m = blockIdx.z, k = threadIdx.x;
    float v = (m ? cw2 : cw1)[l * 65536 + k * 256 + n];
    __nv_bfloat16 hi = __float2bfloat16(v);
    __nv_bfloat16 lo = __float2bfloat16(v - __bfloat162float(hi));
    size_t di = (size_t)l * 65536 + n * 256 + k;
    if (m) { g_cw2hi[di] = hi; g_cw2lo[di] = lo; }
    else   { g_cw1hi[di] = hi; g_cw1lo[di] = lo; }
}

// ---------------- r = relu(edge_attr @ ew1 + eb1) -> fp16 --------------------
__global__ void r_kernel(const float* __restrict__ ea, const float* __restrict__ ew1,
                         const float* __restrict__ eb1) {
    int e0 = blockIdx.x * 32;
    int j = threadIdx.x;
    __shared__ float eas[32 * 8];
    eas[j] = ea[e0 * 8 + j];
    float w[8];
#pragma unroll
    for (int k = 0; k < 8; k++) w[k] = ew1[k * 256 + j];
    float b = eb1[j];
    __syncthreads();
    for (int e = 0; e < 32; e++) {
        float acc = b;
#pragma unroll
        for (int k = 0; k < 8; k++) acc += eas[e * 8 + k] * w[k];
        g_R16[(size_t)(e0 + e) * 256 + j] = __float2half(fmaxf(acc, 0.f));
    }
}

// ---------------- h = silu([x|c] @ in_w + in_b); also z = h ------------------
__global__ void input_proj(const float* __restrict__ x, const float* __restrict__ c,
                           const int* __restrict__ gid, const int* __restrict__ lid,
                           const float* __restrict__ inw, const float* __restrict__ inb) {
    int n0 = blockIdx.x * 8;
    int j = threadIdx.x;
    __shared__ float xs[8 * 16];
    __shared__ float cs[8];
    if (j < 128) xs[j] = x[n0 * 16 + j];
    if (j < 8) { int n = n0 + j; cs[j] = c[gid[n] * PG + lid[n]]; }
    float w[17];
#pragma unroll
    for (int k = 0; k < 17; k++) w[k] = inw[k * 256 + j];
    float b = inb[j];
    __syncthreads();
    for (int n = 0; n < 8; n++) {
        float acc = b + cs[n] * w[16];
#pragma unroll
        for (int k = 0; k < 16; k++) acc += xs[n * 16 + k] * w[k];
        float v = siluf(acc);
        g_h[(n0 + n) * 256 + j] = v;
        g_z[(n0 + n) * 256 + j] = v;
    }
}

// ---------------- edge GEMM (single fp16 term) + fused relu-msg scatter -----
// CTA: 128 edges x 128 cols, K=256 in 4 chunks of 64, 3-stage cp.async pipe.
__global__ void __launch_bounds__(256, 2) edge_mma(int l, const int* __restrict__ eidx) {
    extern __shared__ char sm[];
    uint32_t sbase = smem_u32(sm);
    float* sBias = (float*)(sm + 98304);

    int tid = threadIdx.x, lane = tid & 31, wid = tid >> 5;
    int wm = wid & 3, wn = wid >> 2;
    int row0 = blockIdx.x * 128, col0 = blockIdx.y * 128;

    if (tid < 128) sBias[tid] = g_bl[l * 256 + col0 + tid];

    const uint4* Ag = (const uint4*)g_R16 + (size_t)row0 * 32;
    const uint4* Bg = (const uint4*)g_W16 + (size_t)l * 8192 + (size_t)col0 * 32;

    float acc[16][4];
#pragma unroll
    for (int i = 0; i < 16; i++) { acc[i][0] = 0.f; acc[i][1] = 0.f; acc[i][2] = 0.f; acc[i][3] = 0.f; }

    auto issue = [&](int c, int s) {
        uint32_t sa = sbase + s * 32768;
#pragma unroll
        for (int i = 0; i < 4; i++) {
            int elem = tid + 256 * i;
            int r = elem >> 3, u = elem & 7;
            uint32_t o = swz((uint32_t)(r * 128 + u * 16));
            CPA16(sa + o,         Ag + (size_t)r * 32 + c * 8 + u);
            CPA16(sa + 16384 + o, Bg + (size_t)r * 32 + c * 8 + u);
        }
    };

    issue(0, 0); CPC;
    issue(1, 1); CPC;

#pragma unroll
    for (int c = 0; c < 4; c++) {
        int s = (c < 3) ? c : 0;
        if (c < 3) { CPW1; } else { CPW0; }
        __syncthreads();
        uint32_t sa = sbase + s * 32768;
#pragma unroll
        for (int ks = 0; ks < 4; ks++) {
            uint32_t a0[4], a1[4];
            int kb = ks * 32 + ((lane >> 4) << 4);
            LDSM4(a0, sa + swz((uint32_t)((wm * 32 + (lane & 15)) * 128 + kb)));
            LDSM4(a1, sa + swz((uint32_t)((wm * 32 + 16 + (lane & 15)) * 128 + kb)));
#pragma unroll
            for (int np = 0; np < 4; np++) {
                int g = lane >> 3, li = lane & 7;
                int brow = wn * 64 + np * 16 + ((g >> 1) << 3) + li;
                int bkb = ks * 32 + ((g & 1) << 4);
                uint32_t bh[4];
                LDSM4(bh, sa + 16384 + swz((uint32_t)(brow * 128 + bkb)));
#pragma unroll
                for (int t = 0; t < 2; t++) {
                    mma_f16(acc[0 * 8 + np * 2 + t], a0, bh[2 * t], bh[2 * t + 1]);
                    mma_f16(acc[1 * 8 + np * 2 + t], a1, bh[2 * t], bh[2 * t + 1]);
                }
            }
        }
        if (c < 2) { issue(c + 2, c + 2 == 2 ? 2 : 0); CPC; }
    }

    // epilogue: relu(acc + bias + h[src]) -> red to z[dst]
    int q = lane >> 2;
    int c2 = (lane & 3) * 2;
    int src_[2][2], dst_[2][2];
#pragma unroll
    for (int mt = 0; mt < 2; mt++)
#pragma unroll
        for (int h = 0; h < 2; h++) {
            int e = row0 + wm * 32 + mt * 16 + h * 8 + q;
            src_[mt][h] = eidx[e];
            dst_[mt][h] = eidx[EE + e];
        }
#pragma unroll
    for (int mt = 0; mt < 2; mt++) {
#pragma unroll
        for (int nt = 0; nt < 8; nt++) {
            float* a = acc[mt * 8 + nt];
            int coln = wn * 64 + nt * 8 + c2;
            int col = col0 + coln;
            float2 bb = *(float2*)(sBias + coln);
#pragma unroll
            for (int h = 0; h < 2; h++) {
                const float2 hv = *(const float2*)(g_h + (size_t)src_[mt][h] * 256 + col);
                float v0 = fmaxf(a[2 * h + 0] + bb.x + hv.x, 0.f);
                float v1 = fmaxf(a[2 * h + 1] + bb.y + hv.y, 0.f);
                float* zp = g_z + (size_t)dst_[mt][h] * 256 + col;
                asm volatile("red.global.add.v2.f32 [%0], {%1,%2};"
                             :: "l"(zp), "f"(v0), "f"(v1) : "memory");
            }
        }
    }
}

// ---------------- z -> bf16 hi/lo split (padded to NPAD rows) ----------------
__global__ void z_split() {
    int i4 = blockIdx.x * 256 + threadIdx.x;          // one float4
    if (i4 >= NPAD * 64) return;
    int s4 = i4 < NN * 64 ? i4 : NN * 64 - 1;
    float4 v = ((const float4*)g_z)[s4];
    __nv_bfloat16 h0 = __float2bfloat16(v.x), h1 = __float2bfloat16(v.y);
    __nv_bfloat16 h2 = __float2bfloat16(v.z), h3 = __float2bfloat16(v.w);
    __nv_bfloat162* zh = (__nv_bfloat162*)g_zhi;
    __nv_bfloat162* zl = (__nv_bfloat162*)g_zlo;
    zh[i4 * 2 + 0] = __nv_bfloat162(h0, h1);
    zh[i4 * 2 + 1] = __nv_bfloat162(h2, h3);
    zl[i4 * 2 + 0] = __nv_bfloat162(__float2bfloat16(v.x - __bfloat162float(h0)),
                                    __float2bfloat16(v.y - __bfloat162float(h1)));
    zl[i4 * 2 + 1] = __nv_bfloat162(__float2bfloat16(v.z - __bfloat162float(h2)),
                                    __float2bfloat16(v.w - __bfloat162float(h3)));
}

// ---------------- node GEMM: bf16 3-term mma, 3-stage cp.async ---------------
// MODE 0: z(hi/lo) @ cw1 -> silu -> split to thi/tlo
// MODE 1: t(hi/lo) @ cw2 -> g_hn (fp32)
// All operand pointers resolved in DEVICE code (device symbols must not cross
// the host launch boundary).
template <int MODE>
__global__ void __launch_bounds__(256, 2) node_mma(int l, const float* __restrict__ bias_all) {
    extern __shared__ char sm[];
    uint32_t sbase = smem_u32(sm);
    float* sBias = (float*)(sm + 98304);

    const __nv_bfloat16* Ahi = (MODE == 0) ? g_zhi : g_thi;
    const __nv_bfloat16* Alo = (MODE == 0) ? g_zlo : g_tlo;
    const __nv_bfloat16* Bhi = ((MODE == 0) ? g_cw1hi : g_cw2hi) + (size_t)l * 65536;
    const __nv_bfloat16* Blo = ((MODE == 0) ? g_cw1lo : g_cw2lo) + (size_t)l * 65536;
    const float* bias = bias_all + l * 256;

    int tid = threadIdx.x, lane = tid & 31, wid = tid >> 5;
    int wm = wid & 3, wn = wid >> 2;
    int row0 = blockIdx.x * 128, col0 = blockIdx.y * 128;

    if (tid < 128) sBias[tid] = bias[col0 + tid];

    const uint4* Ah4 = (const uint4*)Ahi + (size_t)row0 * 32;
    const uint4* Al4 = (const uint4*)Alo + (size_t)row0 * 32;
    const uint4* Bh4 = (const uint4*)Bhi + (size_t)col0 * 32;
    const uint4* Bl4 = (const uint4*)Blo + (size_t)col0 * 32;

    float acc[16][4];
#pragma unroll
    for (int i = 0; i < 16; i++) { acc[i][0] = 0.f; acc[i][1] = 0.f; acc[i][2] = 0.f; acc[i][3] = 0.f; }

    auto issue = [&](int c, int s) {
        uint32_t sa = sbase + s * 32768;
#pragma unroll
        for (int i = 0; i < 4; i++) {
            int elem = tid + 256 * i;
            int r = elem >> 3, u = elem & 7;
            const uint4* sA = (u < 4) ? Ah4 : Al4;
            const uint4* sB = (u < 4) ? Bh4 : Bl4;
            uint32_t o = swz((uint32_t)(r * 128 + u * 16));
            CPA16(sa + o,         sA + (size_t)r * 32 + c * 4 + (u & 3));
            CPA16(sa + 16384 + o, sB + (size_t)r * 32 + c * 4 + (u & 3));
        }
    };

    issue(0, 0); CPC;
    issue(1, 1); CPC;

    for (int c = 0; c < 8; c++) {
        int s = c % 3;
        if (c < 7) { CPW1; } else { CPW0; }
        __syncthreads();
        uint32_t sa = sbase + s * 32768;
#pragma unroll
        for (int ks = 0; ks < 2; ks++) {
            uint32_t ah[2][4], al[2][4];
            int kb = ks * 32 + ((lane >> 4) << 4);
#pragma unroll
            for (int mt = 0; mt < 2; mt++) {
                int arow = wm * 32 + mt * 16 + (lane & 15);
                LDSM4(ah[mt], sa + swz((uint32_t)(arow * 128 + kb)));
                LDSM4(al[mt], sa + swz((uint32_t)(arow * 128 + 64 + kb)));
            }
#pragma unroll
            for (int np = 0; np < 4; np++) {
                int g = lane >> 3, li = lane & 7;
                int brow = wn * 64 + np * 16 + ((g >> 1) << 3) + li;
                int bkb = ks * 32 + ((g & 1) << 4);
                uint32_t bh[4], bl[4];
                LDSM4(bh, sa + 16384 + swz((uint32_t)(brow * 128 + bkb)));
                LDSM4(bl, sa + 16384 + swz((uint32_t)(brow * 128 + 64 + bkb)));
#pragma unroll
                for (int t = 0; t < 2; t++) {
#pragma unroll
                    for (int mt = 0; mt < 2; mt++) {
                        float* d = acc[mt * 8 + np * 2 + t];
                        mma_bf16(d, ah[mt], bh[2 * t], bh[2 * t + 1]);
                        mma_bf16(d, ah[mt], bl[2 * t], bl[2 * t + 1]);
                        mma_bf16(d, al[mt], bh[2 * t], bh[2 * t + 1]);
                    }
                }
            }
        }
        if (c < 6) { issue(c + 2, (c + 2) % 3); CPC; }
    }

    int q = lane >> 2;
    int c2 = (lane & 3) * 2;
#pragma unroll
    for (int mt = 0; mt < 2; mt++) {
#pragma unroll
        for (int nt = 0; nt < 8; nt++) {
            float* a = acc[mt * 8 + nt];
            int coln = wn * 64 + nt * 8 + c2;
            int col = col0 + coln;
            float2 bb = *(float2*)(sBias + coln);
#pragma unroll
            for (int h = 0; h < 2; h++) {
                int rr = row0 + wm * 32 + mt * 16 + h * 8 + q;
                float v0 = a[2 * h + 0] + bb.x;
                float v1 = a[2 * h + 1] + bb.y;
                if (MODE == 0) {
                    v0 = siluf(v0); v1 = siluf(v1);
                    __nv_bfloat16 h0 = __float2bfloat16(v0), h1 = __float2bfloat16(v1);
                    size_t o = (size_t)rr * 256 + col;
                    *(__nv_bfloat162*)(g_thi + o) = __nv_bfloat162(h0, h1);
                    *(__nv_bfloat162*)(g_tlo + o) =
                        __nv_bfloat162(__float2bfloat16(v0 - __bfloat162float(h0)),
                                       __float2bfloat16(v1 - __bfloat162float(h1)));
                } else {
                    if (rr < NN) *(float2*)(g_hn + (size_t)rr * 256 + col) = make_float2(v0, v1);
                }
            }
        }
    }
}

// ---------------- LayerNorm + residual silu update; also z = h_next ----------
__global__ void ln_update(int l, const float* __restrict__ lng, const float* __restrict__ lnb) {
    int warp = threadIdx.x >> 5, lane = threadIdx.x & 31;
    int n = blockIdx.x * 8 + warp;
    const float* g = lng + l * 256;
    const float* b = lnb + l * 256;
    const float* row = g_hn + (size_t)n * 256;
    float v[8];
    float s = 0.f, ss = 0.f;
#pragma unroll
    for (int t = 0; t < 8; t++) {
        v[t] = row[lane + 32 * t];
        s += v[t]; ss += v[t] * v[t];
    }
#pragma unroll
    for (int o = 16; o > 0; o >>= 1) {
        s += __shfl_xor_sync(~0u, s, o);
        ss += __shfl_xor_sync(~0u, ss, o);
    }
    float m = s * (1.f / 256.f);
    float var = ss * (1.f / 256.f) - m * m;
    float r = rsqrtf(var + 1e-5f);
    float* hrow = g_h + (size_t)n * 256;
    float* zrow = g_z + (size_t)n * 256;
#pragma unroll
    for (int t = 0; t < 8; t++) {
        int cidx = lane + 32 * t;
        float u = (v[t] - m) * r * g[cidx] + b[cidx];
        float nh = hrow[cidx] + siluf(u);
        hrow[cidx] = nh;
        zrow[cidx] = nh;
    }
}

// ---------------- attention scores ------------------------------------------
__global__ void __launch_bounds__(256) scores_kernel(const float* __restrict__ w1,
                                                     const float* __restrict__ b1,
                                                     const float* __restrict__ w2,
                                                     const float* __restrict__ b2) {
    int n0 = blockIdx.x * 32;
    int j = threadIdx.x;
    __shared__ float hs[32][256];
    __shared__ float part[32][8];
    for (int i = j; i < 32 * 256; i += 256) hs[i >> 8][i & 255] = g_h[(size_t)n0 * 256 + i];
    float acc[32];
#pragma unroll
    for (int n = 0; n < 32; n++) acc[n] = 0.f;
    __syncthreads();
    for (int k = 0; k < 256; k++) {
        float w = w1[k * 256 + j];
#pragma unroll
        for (int n = 0; n < 32; n++) acc[n] += hs[n][k] * w;
    }
    float b1j = b1[j], w2j = w2[j];
    int lane = j & 31, wid = j >> 5;
#pragma unroll
    for (int n = 0; n < 32; n++) {
        float val = tanhf(acc[n] + b1j) * w2j;
#pragma unroll
        for (int o = 16; o > 0; o >>= 1) val += __shfl_xor_sync(~0u, val, o);
        if (lane == 0) part[n][wid] = val;
    }
    __syncthreads();
    if (j < 32) {
        float sres = b2[0];
#pragma unroll
        for (int w = 0; w < 8; w++) sres += part[j][w];
        g_scores[n0 + j] = sres;
    }
}

// ---------------- global softmax stats --------------------------------------
__global__ void softmax_stats() {
    __shared__ float red[1024];
    int t = threadIdx.x;
    float m = -1e30f;
    for (int i = t; i < NN; i += 1024) m = fmaxf(m, g_scores[i]);
    red[t] = m;
    __syncthreads();
    for (int o = 512; o > 0; o >>= 1) {
        if (t < o) red[t] = fmaxf(red[t], red[t + o]);
        __syncthreads();
    }
    float gmax = red[0];
    __syncthreads();
    float s = 0.f;
    for (int i = t; i < NN; i += 1024) s += expf(g_scores[i] - gmax);
    red[t] = s;
    __syncthreads();
    for (int o = 512; o > 0; o >>= 1) {
        if (t < o) red[t] += red[t + o];
        __syncthreads();
    }
    if (t == 0) { g_stats[0] = gmax; g_stats[1] = red[0]; }
}

// ---------------- per-graph renormalized attention --------------------------
__global__ void seg_attn() {
    int g = blockIdx.x, t = threadIdx.x;
    float gmax = g_stats[0], Z = g_stats[1];
    int base = g * PG;
    float s = 0.f;
    for (int i = t; i < PG; i += 256) s += expf(g_scores[base + i] - gmax);
    __shared__ float red[256];
    red[t] = s;
    __syncthreads();
    for (int o = 128; o > 0; o >>= 1) {
        if (t < o) red[t] += red[t + o];
        __syncthreads();
    }
    float denom = red[0] / Z + 1e-8f;
    float scale = 1.f / (Z * denom);
    for (int i = t; i < PG; i += 256) g_attn[base + i] = expf(g_scores[base + i] - gmax) * scale;
    g_pooled[g * 256 + t] = 0.f;
}

// ---------------- weighted pooling ------------------------------------------
__global__ void pool_kernel() {
    int g = blockIdx.x, chunk = blockIdx.y, j = threadIdx.x;
    int base = g * PG + chunk * 250;
    float acc = 0.f;
    for (int i = 0; i < 250; i++)
        acc += g_h[(size_t)(base + i) * 256 + j] * g_attn[base + i];
    atomicAdd(&g_pooled[g * 256 + j], acc);
}

// ---------------- head -------------------------------------------------------
__global__ void head_kernel(const float* __restrict__ hw1, const float* __restrict__ hb1,
                            const float* __restrict__ hw2, const float* __restrict__ hb2,
                            float* __restrict__ out) {
    int g = blockIdx.x, j = threadIdx.x;
    __shared__ float ps[256];
    __shared__ float red[256];
    ps[j] = g_pooled[g * 256 + j];
    __syncthreads();
    float acc = hb1[j];
#pragma unroll 8
    for (int k = 0; k < 256; k++) acc += ps[k] * hw1[k * 256 + j];
    red[j] = siluf(acc) * hw2[j];
    __syncthreads();
    for (int o = 128; o > 0; o >>= 1) {
        if (j < o) red[j] += red[j + o];
        __syncthreads();
    }
    if (j == 0) out[g] = red[0] + hb2[0];
}

// ---------------- launch -----------------------------------------------------
extern "C" void kernel_launch(void* const* d_in, const int* in_sizes, int n_in,
                              void* d_out, int out_size) {
    const float* x    = (const float*)d_in[0];
    const float* ea   = (const float*)d_in[1];
    const float* c    = (const float*)d_in[2];
    const int*   eidx = (const int*)  d_in[3];
    const int*   gid  = (const int*)  d_in[4];
    const int*   lid  = (const int*)  d_in[5];
    const float* ew1  = (const float*)d_in[6];
    const float* eb1  = (const float*)d_in[7];
    const float* ew2  = (const float*)d_in[8];
    const float* eb2  = (const float*)d_in[9];
    const float* inw  = (const float*)d_in[10];
    const float* inb  = (const float*)d_in[11];
    const float* lin_w = (const float*)d_in[12];
    const float* lin_b = (const float*)d_in[13];
    const float* cw1  = (const float*)d_in[14];
    const float* cb1  = (const float*)d_in[15];
    const float* cw2  = (const float*)d_in[16];
    const float* cb2  = (const float*)d_in[17];
    const float* lng  = (const float*)d_in[18];
    const float* lnb  = (const float*)d_in[19];
    const float* paw1 = (const float*)d_in[20];
    const float* pab1 = (const float*)d_in[21];
    const float* paw2 = (const float*)d_in[22];
    const float* pab2 = (const float*)d_in[23];
    const float* hw1  = (const float*)d_in[24];
    const float* hb1  = (const float*)d_in[25];
    const float* hw2  = (const float*)d_in[26];
    const float* hb2  = (const float*)d_in[27];
    float* out = (float*)d_out;

    static int attr_done = 0;
    if (!attr_done) {
        cudaFuncSetAttribute((const void*)edge_mma,
                             cudaFuncAttributeMaxDynamicSharedMemorySize, PIPE_SMEM);
        cudaFuncSetAttribute((const void*)node_mma<0>,
                             cudaFuncAttributeMaxDynamicSharedMemorySize, PIPE_SMEM);
        cudaFuncSetAttribute((const void*)node_mma<1>,
                             cudaFuncAttributeMaxDynamicSharedMemorySize, PIPE_SMEM);
        attr_done = 1;
    }

    prep_W<<<LL * 256, 256>>>(ew2, lin_w);
    prep_bl<<<LL, 256>>>(eb2, lin_w, lin_b);
    prep_nw<<<dim3(256, LL, 2), 256>>>(cw1, cw2);
    r_kernel<<<EE / 32, 256>>>(ea, ew1, eb1);
    input_proj<<<NN / 8, 256>>>(x, c, gid, lid, inw, inb);

    for (int l = 0; l < LL; l++) {
        edge_mma<<<dim3(EE / 128, 2), 256, PIPE_SMEM>>>(l, eidx);
        z_split<<<(NPAD * 64 + 255) / 256, 256>>>();
        node_mma<0><<<dim3(NPAD / 128, 2), 256, PIPE_SMEM>>>(l, cb1);
        node_mma<1><<<dim3(NPAD / 128, 2), 256, PIPE_SMEM>>>(l, cb2);
        ln_update<<<NN / 8, 256>>>(l, lng, lnb);
    }

    scores_kernel<<<NN / 32, 256>>>(paw1, pab1, paw2, pab2);
    softmax_stats<<<1, 1024>>>();
    seg_attn<<<GB, 256>>>();
    pool_kernel<<<dim3(GB, 4), 256>>>();
    head_kernel<<<GB, 256>>>(hw1, hb1, hw2, hb2, out);
    (void)in_sizes; (void)n_in; (void)out_size;
}

// round 6
// speedup vs baseline: 3.8562x; 1.0274x over previous
#include <cuda_runtime.h>
#include <cuda_bf16.h>
#include <cuda_fp16.h>
#include <math.h>
#include <stdint.h>

#define NN 20000
#define EE 320000
#define HH 256
#define LL 6
#define GB 20
#define PG 1000
#define NPAD 20096   // 157*128

// ---------------- scratch ----------------------------------------------------
__device__ __half g_R16[(size_t)EE * HH];        // fp16 edge features
__device__ __half g_W16[LL * HH * HH];           // fp16 folded edge weights [l][n][k]
__device__ float g_bl[LL * HH];
__device__ float g_h[NN * HH];
__device__ float g_z[NN * HH];
__device__ float g_hn[NN * HH];
__device__ __nv_bfloat16 g_zhi[NPAD * HH];
__device__ __nv_bfloat16 g_thi[NPAD * HH];
__device__ __nv_bfloat16 g_cw1hi[LL * HH * HH], g_cw1lo[LL * HH * HH];  // [l][n][k]
__device__ __nv_bfloat16 g_cw2hi[LL * HH * HH], g_cw2lo[LL * HH * HH];
__device__ float g_scores[NN];
__device__ float g_attn[NN];
__device__ float g_stats[2];
__device__ float g_pooled[GB * HH];

__device__ __forceinline__ float siluf(float x) { return x / (1.f + expf(-x)); }

__device__ __forceinline__ uint32_t smem_u32(const void* p) {
    uint32_t a;
    asm("{ .reg .u64 t; cvta.to.shared.u64 t, %1; cvt.u32.u64 %0, t; }" : "=r"(a) : "l"(p));
    return a;
}
__device__ __forceinline__ uint32_t swz(uint32_t o) { return o ^ ((o >> 3) & 0x70); }

#define LDSM4(r, addr) \
    asm volatile("ldmatrix.sync.aligned.m8n8.x4.shared.b16 {%0,%1,%2,%3}, [%4];" \
        : "=r"((r)[0]), "=r"((r)[1]), "=r"((r)[2]), "=r"((r)[3]) : "r"(addr))

__device__ __forceinline__ void mma_bf16(float* d, const uint32_t* a, uint32_t b0, uint32_t b1) {
    asm volatile("mma.sync.aligned.m16n8k16.row.col.f32.bf16.bf16.f32 "
        "{%0,%1,%2,%3}, {%4,%5,%6,%7}, {%8,%9}, {%0,%1,%2,%3};"
        : "+f"(d[0]), "+f"(d[1]), "+f"(d[2]), "+f"(d[3])
        : "r"(a[0]), "r"(a[1]), "r"(a[2]), "r"(a[3]), "r"(b0), "r"(b1));
}
__device__ __forceinline__ void mma_f16(float* d, const uint32_t* a, uint32_t b0, uint32_t b1) {
    asm volatile("mma.sync.aligned.m16n8k16.row.col.f32.f16.f16.f32 "
        "{%0,%1,%2,%3}, {%4,%5,%6,%7}, {%8,%9}, {%0,%1,%2,%3};"
        : "+f"(d[0]), "+f"(d[1]), "+f"(d[2]), "+f"(d[3])
        : "r"(a[0]), "r"(a[1]), "r"(a[2]), "r"(a[3]), "r"(b0), "r"(b1));
}

#define CPA16(d, s) asm volatile("cp.async.cg.shared.global [%0], [%1], 16;" :: "r"(d), "l"(s) : "memory")
#define CPC        asm volatile("cp.async.commit_group;" ::: "memory")
#define CPW1       asm volatile("cp.async.wait_group 1;" ::: "memory")
#define CPW0       asm volatile("cp.async.wait_group 0;" ::: "memory")

#define PIPE_SMEM (98304 + 512)

// ---------------- weight folding: W16_l = (ew2 @ lin_w[l])^T fp16 -----------
__global__ void prep_W(const float* __restrict__ ew2, const float* __restrict__ lin_w) {
    int l = blockIdx.x >> 8;
    int i = blockIdx.x & 255;   // K index
    int j = threadIdx.x;        // N index
    __shared__ float er[256];
    er[j] = ew2[i * 256 + j];
    __syncthreads();
    const float* lw = lin_w + l * 65536;
    float acc = 0.f;
#pragma unroll 8
    for (int m = 0; m < 256; m++) acc += er[m] * lw[m * 256 + j];
    g_W16[l * 65536 + j * 256 + i] = __float2half(acc);
}

__global__ void prep_bl(const float* __restrict__ eb2, const float* __restrict__ lin_w,
                        const float* __restrict__ lin_b) {
    int l = blockIdx.x;
    int j = threadIdx.x;
    const float* lw = lin_w + l * 65536;
    float acc = lin_b[l * 256 + j];
#pragma unroll 8
    for (int m = 0; m < 256; m++) acc += eb2[m] * lw[m * 256 + j];
    g_bl[l * 256 + j] = acc;
}

// ---------------- node weight transpose + bf16 split -------------------------
__global__ void prep_nw(const float* __restrict__ cw1, const float* __restrict__ cw2) {
    int n = blockIdx.x, l = blockIdx.y, m = blockIdx.z, k = threadIdx.x;
    float v = (m ? cw2 : cw1)[l * 65536 + k * 256 + n];
    __nv_bfloat16 hi = __float2bfloat16(v);
    __nv_bfloat16 lo = __float2bfloat16(v - __bfloat162float(hi));
    size_t di = (size_t)l * 65536 + n * 256 + k;
    if (m) { g_cw2hi[di] = hi; g_cw2lo[di] = lo; }
    else   { g_cw1hi[di] = hi; g_cw1lo[di] = lo; }
}

// ---------------- r = relu(edge_attr @ ew1 + eb1) -> fp16 (half2 stores) -----
__global__ void r_kernel(const float* __restrict__ ea, const float* __restrict__ ew1,
                         const float* __restrict__ eb1) {
    int e0 = blockIdx.x * 32;
    int j = threadIdx.x;            // 0..127 -> cols 2j, 2j+1
    __shared__ float eas[256];
    eas[j] = ea[e0 * 8 + j];
    eas[j + 128] = ea[e0 * 8 + 128 + j];
    float w0[8], w1[8];
#pragma unroll
    for (int k = 0; k < 8; k++) {
        w0[k] = ew1[k * 256 + 2 * j];
        w1[k] = ew1[k * 256 + 2 * j + 1];
    }
    float b0 = eb1[2 * j], b1 = eb1[2 * j + 1];
    __syncthreads();
    __half2* out = (__half2*)g_R16;
    for (int e = 0; e < 32; e++) {
        float a0 = b0, a1 = b1;
#pragma unroll
        for (int k = 0; k < 8; k++) {
            float v = eas[e * 8 + k];
            a0 += v * w0[k];
            a1 += v * w1[k];
        }
        out[(size_t)(e0 + e) * 128 + j] =
            __floats2half2_rn(fmaxf(a0, 0.f), fmaxf(a1, 0.f));
    }
}

// ---------------- h = silu([x|c] @ in_w + in_b); also z = h ------------------
__global__ void input_proj(const float* __restrict__ x, const float* __restrict__ c,
                           const int* __restrict__ gid, const int* __restrict__ lid,
                           const float* __restrict__ inw, const float* __restrict__ inb) {
    int n0 = blockIdx.x * 8;
    int j = threadIdx.x;
    __shared__ float xs[8 * 16];
    __shared__ float cs[8];
    if (j < 128) xs[j] = x[n0 * 16 + j];
    if (j < 8) { int n = n0 + j; cs[j] = c[gid[n] * PG + lid[n]]; }
    float w[17];
#pragma unroll
    for (int k = 0; k < 17; k++) w[k] = inw[k * 256 + j];
    float b = inb[j];
    __syncthreads();
    for (int n = 0; n < 8; n++) {
        float acc = b + cs[n] * w[16];
#pragma unroll
        for (int k = 0; k < 16; k++) acc += xs[n * 16 + k] * w[k];
        float v = siluf(acc);
        g_h[(n0 + n) * 256 + j] = v;
        g_z[(n0 + n) * 256 + j] = v;
    }
}

// ---------------- edge GEMM (single fp16 term) + fused relu-msg scatter -----
// grid (2, EE/128): col-block pairs adjacent in schedule -> R rows hit L2 on
// the second read. Epilogue: paired-lane v4 red atomics.
__global__ void __launch_bounds__(256, 2) edge_mma(int l, const int* __restrict__ eidx) {
    extern __shared__ char sm[];
    uint32_t sbase = smem_u32(sm);
    float* sBias = (float*)(sm + 98304);

    int tid = threadIdx.x, lane = tid & 31, wid = tid >> 5;
    int wm = wid & 3, wn = wid >> 2;
    int col0 = blockIdx.x * 128, row0 = blockIdx.y * 128;

    if (tid < 128) sBias[tid] = g_bl[l * 256 + col0 + tid];

    const uint4* Ag = (const uint4*)g_R16 + (size_t)row0 * 32;
    const uint4* Bg = (const uint4*)g_W16 + (size_t)l * 8192 + (size_t)col0 * 32;

    float acc[16][4];
#pragma unroll
    for (int i = 0; i < 16; i++) { acc[i][0] = 0.f; acc[i][1] = 0.f; acc[i][2] = 0.f; acc[i][3] = 0.f; }

    auto issue = [&](int c, int s) {
        uint32_t sa = sbase + s * 32768;
#pragma unroll
        for (int i = 0; i < 4; i++) {
            int elem = tid + 256 * i;
            int r = elem >> 3, u = elem & 7;
            uint32_t o = swz((uint32_t)(r * 128 + u * 16));
            CPA16(sa + o,         Ag + (size_t)r * 32 + c * 8 + u);
            CPA16(sa + 16384 + o, Bg + (size_t)r * 32 + c * 8 + u);
        }
    };

    issue(0, 0); CPC;
    issue(1, 1); CPC;

#pragma unroll
    for (int c = 0; c < 4; c++) {
        int s = (c < 3) ? c : 0;
        if (c < 3) { CPW1; } else { CPW0; }
        __syncthreads();
        uint32_t sa = sbase + s * 32768;
#pragma unroll
        for (int ks = 0; ks < 4; ks++) {
            uint32_t a0[4], a1[4];
            int kb = ks * 32 + ((lane >> 4) << 4);
            LDSM4(a0, sa + swz((uint32_t)((wm * 32 + (lane & 15)) * 128 + kb)));
            LDSM4(a1, sa + swz((uint32_t)((wm * 32 + 16 + (lane & 15)) * 128 + kb)));
#pragma unroll
            for (int np = 0; np < 4; np++) {
                int g = lane >> 3, li = lane & 7;
                int brow = wn * 64 + np * 16 + ((g >> 1) << 3) + li;
                int bkb = ks * 32 + ((g & 1) << 4);
                uint32_t bh[4];
                LDSM4(bh, sa + 16384 + swz((uint32_t)(brow * 128 + bkb)));
#pragma unroll
                for (int t = 0; t < 2; t++) {
                    mma_f16(acc[0 * 8 + np * 2 + t], a0, bh[2 * t], bh[2 * t + 1]);
                    mma_f16(acc[1 * 8 + np * 2 + t], a1, bh[2 * t], bh[2 * t + 1]);
                }
            }
        }
        if (c < 2) { issue(c + 2, c + 2 == 2 ? 2 : 0); CPC; }
    }

    // epilogue: relu(acc + bias + h[src]) -> paired-lane v4 red to z[dst]
    int q = lane >> 2;
    int c2 = (lane & 3) * 2;
    int src_[2][2], dst_[2][2];
#pragma unroll
    for (int mt = 0; mt < 2; mt++)
#pragma unroll
        for (int h = 0; h < 2; h++) {
            int e = row0 + wm * 32 + mt * 16 + h * 8 + q;
            src_[mt][h] = eidx[e];
            dst_[mt][h] = eidx[EE + e];
        }
#pragma unroll
    for (int mt = 0; mt < 2; mt++) {
#pragma unroll
        for (int nt = 0; nt < 8; nt++) {
            float* a = acc[mt * 8 + nt];
            int coln = wn * 64 + nt * 8 + c2;
            int col = col0 + coln;
            float2 bb = *(float2*)(sBias + coln);
#pragma unroll
            for (int h = 0; h < 2; h++) {
                const float2 hv = *(const float2*)(g_h + (size_t)src_[mt][h] * 256 + col);
                float v0 = fmaxf(a[2 * h + 0] + bb.x + hv.x, 0.f);
                float v1 = fmaxf(a[2 * h + 1] + bb.y + hv.y, 0.f);
                float e0 = __shfl_xor_sync(~0u, v0, 1);
                float e1 = __shfl_xor_sync(~0u, v1, 1);
                if (!(lane & 1)) {
                    float* zp = g_z + (size_t)dst_[mt][h] * 256 + col;
                    asm volatile("red.global.add.v4.f32 [%0], {%1,%2,%3,%4};"
                                 :: "l"(zp), "f"(v0), "f"(v1), "f"(e0), "f"(e1) : "memory");
                }
            }
        }
    }
}

// ---------------- z -> bf16 (padded to NPAD rows) -----------------------------
__global__ void z_split() {
    int i4 = blockIdx.x * 256 + threadIdx.x;          // one float4
    if (i4 >= NPAD * 64) return;
    int s4 = i4 < NN * 64 ? i4 : NN * 64 - 1;
    float4 v = ((const float4*)g_z)[s4];
    __nv_bfloat162* zh = (__nv_bfloat162*)g_zhi;
    zh[i4 * 2 + 0] = __nv_bfloat162(__float2bfloat16(v.x), __float2bfloat16(v.y));
    zh[i4 * 2 + 1] = __nv_bfloat162(__float2bfloat16(v.z), __float2bfloat16(v.w));
}

// ---------------- node GEMM: bf16 A, W hi+lo (2-term), 2-stage cp.async ------
// MODE 0: zhi @ cw1 -> silu -> thi (bf16). MODE 1: thi @ cw2 -> g_hn (fp32).
// Stage: A 16KB @0, Bhi 16KB @16384, Blo 16KB @32768; stride 49152; 2 stages.
template <int MODE>
__global__ void __launch_bounds__(256, 2) node_mma(int l, const float* __restrict__ bias_all) {
    extern __shared__ char sm[];
    uint32_t sbase = smem_u32(sm);
    float* sBias = (float*)(sm + 98304);

    const __nv_bfloat16* A = (MODE == 0) ? g_zhi : g_thi;
    const __nv_bfloat16* Bhi = ((MODE == 0) ? g_cw1hi : g_cw2hi) + (size_t)l * 65536;
    const __nv_bfloat16* Blo = ((MODE == 0) ? g_cw1lo : g_cw2lo) + (size_t)l * 65536;
    const float* bias = bias_all + l * 256;

    int tid = threadIdx.x, lane = tid & 31, wid = tid >> 5;
    int wm = wid & 3, wn = wid >> 2;
    int col0 = blockIdx.x * 128, row0 = blockIdx.y * 128;

    if (tid < 128) sBias[tid] = bias[col0 + tid];

    const uint4* A4 = (const uint4*)A + (size_t)row0 * 32;
    const uint4* Bh4 = (const uint4*)Bhi + (size_t)col0 * 32;
    const uint4* Bl4 = (const uint4*)Blo + (size_t)col0 * 32;

    float acc[16][4];
#pragma unroll
    for (int i = 0; i < 16; i++) { acc[i][0] = 0.f; acc[i][1] = 0.f; acc[i][2] = 0.f; acc[i][3] = 0.f; }

    auto issue = [&](int c, int s) {
        uint32_t sa = sbase + s * 49152;
#pragma unroll
        for (int i = 0; i < 4; i++) {
            int elem = tid + 256 * i;
            int r = elem >> 3, u = elem & 7;
            uint32_t o = swz((uint32_t)(r * 128 + u * 16));
            CPA16(sa + o,         A4  + (size_t)r * 32 + c * 8 + u);
            CPA16(sa + 16384 + o, Bh4 + (size_t)r * 32 + c * 8 + u);
            CPA16(sa + 32768 + o, Bl4 + (size_t)r * 32 + c * 8 + u);
        }
    };

    issue(0, 0); CPC;
    issue(1, 1); CPC;

#pragma unroll
    for (int c = 0; c < 4; c++) {
        if (c < 3) { CPW1; } else { CPW0; }
        __syncthreads();
        uint32_t sa = sbase + (c & 1) * 49152;
#pragma unroll
        for (int ks = 0; ks < 4; ks++) {
            uint32_t a0[4], a1[4];
            int kb = ks * 32 + ((lane >> 4) << 4);
            LDSM4(a0, sa + swz((uint32_t)((wm * 32 + (lane & 15)) * 128 + kb)));
            LDSM4(a1, sa + swz((uint32_t)((wm * 32 + 16 + (lane & 15)) * 128 + kb)));
#pragma unroll
            for (int np = 0; np < 4; np++) {
                int g = lane >> 3, li = lane & 7;
                int brow = wn * 64 + np * 16 + ((g >> 1) << 3) + li;
                int bkb = ks * 32 + ((g & 1) << 4);
                uint32_t bh[4], bl[4];
                LDSM4(bh, sa + 16384 + swz((uint32_t)(brow * 128 + bkb)));
                LDSM4(bl, sa + 32768 + swz((uint32_t)(brow * 128 + bkb)));
#pragma unroll
                for (int t = 0; t < 2; t++) {
                    mma_bf16(acc[0 * 8 + np * 2 + t], a0, bh[2 * t], bh[2 * t + 1]);
                    mma_bf16(acc[0 * 8 + np * 2 + t], a0, bl[2 * t], bl[2 * t + 1]);
                    mma_bf16(acc[1 * 8 + np * 2 + t], a1, bh[2 * t], bh[2 * t + 1]);
                    mma_bf16(acc[1 * 8 + np * 2 + t], a1, bl[2 * t], bl[2 * t + 1]);
                }
            }
        }
        if (c < 2) { __syncthreads(); issue(c + 2, c & 1); CPC; }
    }

    int q = lane >> 2;
    int c2 = (lane & 3) * 2;
#pragma unroll
    for (int mt = 0; mt < 2; mt++) {
#pragma unroll
        for (int nt = 0; nt < 8; nt++) {
            float* a = acc[mt * 8 + nt];
            int coln = wn * 64 + nt * 8 + c2;
            int col = col0 + coln;
            float2 bb = *(float2*)(sBias + coln);
#pragma unroll
            for (int h = 0; h < 2; h++) {
                int rr = row0 + wm * 32 + mt * 16 + h * 8 + q;
                float v0 = a[2 * h + 0] + bb.x;
                float v1 = a[2 * h + 1] + bb.y;
                if (MODE == 0) {
                    v0 = siluf(v0); v1 = siluf(v1);
                    *(__nv_bfloat162*)(g_thi + (size_t)rr * 256 + col) =
                        __nv_bfloat162(__float2bfloat16(v0), __float2bfloat16(v1));
                } else {
                    if (rr < NN) *(float2*)(g_hn + (size_t)rr * 256 + col) = make_float2(v0, v1);
                }
            }
        }
    }
}

// ---------------- LayerNorm + residual silu update; also z = h_next ----------
__global__ void ln_update(int l, const float* __restrict__ lng, const float* __restrict__ lnb) {
    int warp = threadIdx.x >> 5, lane = threadIdx.x & 31;
    int n = blockIdx.x * 8 + warp;
    const float* g = lng + l * 256;
    const float* b = lnb + l * 256;
    const float* row = g_hn + (size_t)n * 256;
    float v[8];
    float s = 0.f, ss = 0.f;
#pragma unroll
    for (int t = 0; t < 8; t++) {
        v[t] = row[lane + 32 * t];
        s += v[t]; ss += v[t] * v[t];
    }
#pragma unroll
    for (int o = 16; o > 0; o >>= 1) {
        s += __shfl_xor_sync(~0u, s, o);
        ss += __shfl_xor_sync(~0u, ss, o);
    }
    float m = s * (1.f / 256.f);
    float var = ss * (1.f / 256.f) - m * m;
    float r = rsqrtf(var + 1e-5f);
    float* hrow = g_h + (size_t)n * 256;
    float* zrow = g_z + (size_t)n * 256;
#pragma unroll
    for (int t = 0; t < 8; t++) {
        int cidx = lane + 32 * t;
        float u = (v[t] - m) * r * g[cidx] + b[cidx];
        float nh = hrow[cidx] + siluf(u);
        hrow[cidx] = nh;
        zrow[cidx] = nh;
    }
}

// ---------------- attention scores ------------------------------------------
__global__ void __launch_bounds__(256) scores_kernel(const float* __restrict__ w1,
                                                     const float* __restrict__ b1,
                                                     const float* __restrict__ w2,
                                                     const float* __restrict__ b2) {
    int n0 = blockIdx.x * 32;
    int j = threadIdx.x;
    __shared__ float hs[32][256];
    __shared__ float part[32][8];
    for (int i = j; i < 32 * 256; i += 256) hs[i >> 8][i & 255] = g_h[(size_t)n0 * 256 + i];
    float acc[32];
#pragma unroll
    for (int n = 0; n < 32; n++) acc[n] = 0.f;
    __syncthreads();
    for (int k = 0; k < 256; k++) {
        float w = w1[k * 256 + j];
#pragma unroll
        for (int n = 0; n < 32; n++) acc[n] += hs[n][k] * w;
    }
    float b1j = b1[j], w2j = w2[j];
    int lane = j & 31, wid = j >> 5;
#pragma unroll
    for (int n = 0; n < 32; n++) {
        float val = tanhf(acc[n] + b1j) * w2j;
#pragma unroll
        for (int o = 16; o > 0; o >>= 1) val += __shfl_xor_sync(~0u, val, o);
        if (lane == 0) part[n][wid] = val;
    }
    __syncthreads();
    if (j < 32) {
        float sres = b2[0];
#pragma unroll
        for (int w = 0; w < 8; w++) sres += part[j][w];
        g_scores[n0 + j] = sres;
    }
}

// ---------------- global softmax stats --------------------------------------
__global__ void softmax_stats() {
    __shared__ float red[1024];
    int t = threadIdx.x;
    float m = -1e30f;
    for (int i = t; i < NN; i += 1024) m = fmaxf(m, g_scores[i]);
    red[t] = m;
    __syncthreads();
    for (int o = 512; o > 0; o >>= 1) {
        if (t < o) red[t] = fmaxf(red[t], red[t + o]);
        __syncthreads();
    }
    float gmax = red[0];
    __syncthreads();
    float s = 0.f;
    for (int i = t; i < NN; i += 1024) s += expf(g_scores[i] - gmax);
    red[t] = s;
    __syncthreads();
    for (int o = 512; o > 0; o >>= 1) {
        if (t < o) red[t] += red[t + o];
        __syncthreads();
    }
    if (t == 0) { g_stats[0] = gmax; g_stats[1] = red[0]; }
}

// ---------------- per-graph renormalized attention --------------------------
__global__ void seg_attn() {
    int g = blockIdx.x, t = threadIdx.x;
    float gmax = g_stats[0], Z = g_stats[1];
    int base = g * PG;
    float s = 0.f;
    for (int i = t; i < PG; i += 256) s += expf(g_scores[base + i] - gmax);
    __shared__ float red[256];
    red[t] = s;
    __syncthreads();
    for (int o = 128; o > 0; o >>= 1) {
        if (t < o) red[t] += red[t + o];
        __syncthreads();
    }
    float denom = red[0] / Z + 1e-8f;
    float scale = 1.f / (Z * denom);
    for (int i = t; i < PG; i += 256) g_attn[base + i] = expf(g_scores[base + i] - gmax) * scale;
    g_pooled[g * 256 + t] = 0.f;
}

// ---------------- weighted pooling ------------------------------------------
__global__ void pool_kernel() {
    int g = blockIdx.x, chunk = blockIdx.y, j = threadIdx.x;
    int base = g * PG + chunk * 250;
    float acc = 0.f;
    for (int i = 0; i < 250; i++)
        acc += g_h[(size_t)(base + i) * 256 + j] * g_attn[base + i];
    atomicAdd(&g_pooled[g * 256 + j], acc);
}

// ---------------- head -------------------------------------------------------
__global__ void head_kernel(const float* __restrict__ hw1, const float* __restrict__ hb1,
                            const float* __restrict__ hw2, const float* __restrict__ hb2,
                            float* __restrict__ out) {
    int g = blockIdx.x, j = threadIdx.x;
    __shared__ float ps[256];
    __shared__ float red[256];
    ps[j] = g_pooled[g * 256 + j];
    __syncthreads();
    float acc = hb1[j];
#pragma unroll 8
    for (int k = 0; k < 256; k++) acc += ps[k] * hw1[k * 256 + j];
    red[j] = siluf(acc) * hw2[j];
    __syncthreads();
    for (int o = 128; o > 0; o >>= 1) {
        if (j < o) red[j] += red[j + o];
        __syncthreads();
    }
    if (j == 0) out[g] = red[0] + hb2[0];
}

// ---------------- launch -----------------------------------------------------
extern "C" void kernel_launch(void* const* d_in, const int* in_sizes, int n_in,
                              void* d_out, int out_size) {
    const float* x    = (const float*)d_in[0];
    const float* ea   = (const float*)d_in[1];
    const float* c    = (const float*)d_in[2];
    const int*   eidx = (const int*)  d_in[3];
    const int*   gid  = (const int*)  d_in[4];
    const int*   lid  = (const int*)  d_in[5];
    const float* ew1  = (const float*)d_in[6];
    const float* eb1  = (const float*)d_in[7];
    const float* ew2  = (const float*)d_in[8];
    const float* eb2  = (const float*)d_in[9];
    const float* inw  = (const float*)d_in[10];
    const float* inb  = (const float*)d_in[11];
    const float* lin_w = (const float*)d_in[12];
    const float* lin_b = (const float*)d_in[13];
    const float* cw1  = (const float*)d_in[14];
    const float* cb1  = (const float*)d_in[15];
    const float* cw2  = (const float*)d_in[16];
    const float* cb2  = (const float*)d_in[17];
    const float* lng  = (const float*)d_in[18];
    const float* lnb  = (const float*)d_in[19];
    const float* paw1 = (const float*)d_in[20];
    const float* pab1 = (const float*)d_in[21];
    const float* paw2 = (const float*)d_in[22];
    const float* pab2 = (const float*)d_in[23];
    const float* hw1  = (const float*)d_in[24];
    const float* hb1  = (const float*)d_in[25];
    const float* hw2  = (const float*)d_in[26];
    const float* hb2  = (const float*)d_in[27];
    float* out = (float*)d_out;

    static int attr_done = 0;
    if (!attr_done) {
        cudaFuncSetAttribute((const void*)edge_mma,
                             cudaFuncAttributeMaxDynamicSharedMemorySize, PIPE_SMEM);
        cudaFuncSetAttribute((const void*)node_mma<0>,
                             cudaFuncAttributeMaxDynamicSharedMemorySize, PIPE_SMEM);
        cudaFuncSetAttribute((const void*)node_mma<1>,
                             cudaFuncAttributeMaxDynamicSharedMemorySize, PIPE_SMEM);
        attr_done = 1;
    }

    prep_W<<<LL * 256, 256>>>(ew2, lin_w);
    prep_bl<<<LL, 256>>>(eb2, lin_w, lin_b);
    prep_nw<<<dim3(256, LL, 2), 256>>>(cw1, cw2);
    r_kernel<<<EE / 32, 128>>>(ea, ew1, eb1);
    input_proj<<<NN / 8, 256>>>(x, c, gid, lid, inw, inb);

    for (int l = 0; l < LL; l++) {
        edge_mma<<<dim3(2, EE / 128), 256, PIPE_SMEM>>>(l, eidx);
        z_split<<<(NPAD * 64 + 255) / 256, 256>>>();
        node_mma<0><<<dim3(2, NPAD / 128), 256, PIPE_SMEM>>>(l, cb1);
        node_mma<1><<<dim3(2, NPAD / 128), 256, PIPE_SMEM>>>(l, cb2);
        ln_update<<<NN / 8, 256>>>(l, lng, lnb);
    }

    scores_kernel<<<NN / 32, 256>>>(paw1, pab1, paw2, pab2);
    softmax_stats<<<1, 1024>>>();
    seg_attn<<<GB, 256>>>();
    pool_kernel<<<dim3(GB, 4), 256>>>();
    head_kernel<<<GB, 256>>>(hw1, hb1, hw2, hb2, out);
    (void)in_sizes; (void)n_in; (void)out_size;
}

// round 8
// speedup vs baseline: 4.1042x; 1.0643x over previous
#include <cuda_runtime.h>
#include <cuda_bf16.h>
#include <cuda_fp16.h>
#include <math.h>
#include <stdint.h>

#define NN 20000
#define EE 320000
#define HH 256
#define LL 6
#define GB 20
#define PG 1000
#define NPAD 20096   // 157*128

// ---------------- scratch ----------------------------------------------------
__device__ __half g_R16[(size_t)EE * HH];        // fp16 edge features
__device__ __half g_W16[LL * HH * HH];           // fp16 folded edge weights [l][n][k]
__device__ float g_bl[LL * HH];
__device__ float g_h[NN * HH];
__device__ float g_z[NPAD * HH];                 // fp32 accumulation target (pad rows stay 0)
__device__ float g_hn[NN * HH];
__device__ __nv_bfloat16 g_zhi[NPAD * HH];       // bf16 of final h (for scores)
__device__ __nv_bfloat16 g_thi[NPAD * HH];
__device__ __nv_bfloat16 g_cw1hi[LL * HH * HH], g_cw1lo[LL * HH * HH];  // [l][n][k]
__device__ __nv_bfloat16 g_cw2hi[LL * HH * HH], g_cw2lo[LL * HH * HH];
__device__ __nv_bfloat16 g_pahi[HH * HH], g_palo[HH * HH];              // paw1^T split
__device__ float g_scores[NN];
__device__ float g_attn[NN];
__device__ float g_stats[2];
__device__ float g_pooled[GB * HH];

__device__ __forceinline__ float siluf(float x) { return x / (1.f + expf(-x)); }

__device__ __forceinline__ uint32_t smem_u32(const void* p) {
    uint32_t a;
    asm("{ .reg .u64 t; cvta.to.shared.u64 t, %1; cvt.u32.u64 %0, t; }" : "=r"(a) : "l"(p));
    return a;
}
__device__ __forceinline__ uint32_t swz(uint32_t o)   { return o ^ ((o >> 3) & 0x70); }
__device__ __forceinline__ uint32_t swz64(uint32_t o) { return o ^ ((o >> 3) & 0x30); }

#define LDSM4(r, addr) \
    asm volatile("ldmatrix.sync.aligned.m8n8.x4.shared.b16 {%0,%1,%2,%3}, [%4];" \
        : "=r"((r)[0]), "=r"((r)[1]), "=r"((r)[2]), "=r"((r)[3]) : "r"(addr))

__device__ __forceinline__ void mma_bf16(float* d, const uint32_t* a, uint32_t b0, uint32_t b1) {
    asm volatile("mma.sync.aligned.m16n8k16.row.col.f32.bf16.bf16.f32 "
        "{%0,%1,%2,%3}, {%4,%5,%6,%7}, {%8,%9}, {%0,%1,%2,%3};"
        : "+f"(d[0]), "+f"(d[1]), "+f"(d[2]), "+f"(d[3])
        : "r"(a[0]), "r"(a[1]), "r"(a[2]), "r"(a[3]), "r"(b0), "r"(b1));
}
__device__ __forceinline__ void mma_f16(float* d, const uint32_t* a, uint32_t b0, uint32_t b1) {
    asm volatile("mma.sync.aligned.m16n8k16.row.col.f32.f16.f16.f32 "
        "{%0,%1,%2,%3}, {%4,%5,%6,%7}, {%8,%9}, {%0,%1,%2,%3};"
        : "+f"(d[0]), "+f"(d[1]), "+f"(d[2]), "+f"(d[3])
        : "r"(a[0]), "r"(a[1]), "r"(a[2]), "r"(a[3]), "r"(b0), "r"(b1));
}

#define CPA16(d, s) asm volatile("cp.async.cg.shared.global [%0], [%1], 16;" :: "r"(d), "l"(s) : "memory")
#define CPC        asm volatile("cp.async.commit_group;" ::: "memory")
#define CPW1       asm volatile("cp.async.wait_group 1;" ::: "memory")
#define CPW0       asm volatile("cp.async.wait_group 0;" ::: "memory")

#define PIPE_SMEM (98304 + 1024)
#define NODE0_SMEM (2 * 24576 + 512)

// ---------------- weight folding: W16_l = (ew2 @ lin_w[l])^T fp16 -----------
__global__ void prep_W(const float* __restrict__ ew2, const float* __restrict__ lin_w) {
    int l = blockIdx.x >> 8;
    int i = blockIdx.x & 255;   // K index
    int j = threadIdx.x;        // N index
    __shared__ float er[256];
    er[j] = ew2[i * 256 + j];
    __syncthreads();
    const float* lw = lin_w + l * 65536;
    float acc = 0.f;
#pragma unroll 8
    for (int m = 0; m < 256; m++) acc += er[m] * lw[m * 256 + j];
    g_W16[l * 65536 + j * 256 + i] = __float2half(acc);
}

__global__ void prep_bl(const float* __restrict__ eb2, const float* __restrict__ lin_w,
                        const float* __restrict__ lin_b) {
    int l = blockIdx.x;
    int j = threadIdx.x;
    const float* lw = lin_w + l * 65536;
    float acc = lin_b[l * 256 + j];
#pragma unroll 8
    for (int m = 0; m < 256; m++) acc += eb2[m] * lw[m * 256 + j];
    g_bl[l * 256 + j] = acc;
}

// ---------------- node weight transpose + bf16 split -------------------------
__global__ void prep_nw(const float* __restrict__ cw1, const float* __restrict__ cw2) {
    int n = blockIdx.x, l = blockIdx.y, m = blockIdx.z, k = threadIdx.x;
    float v = (m ? cw2 : cw1)[l * 65536 + k * 256 + n];
    __nv_bfloat16 hi = __float2bfloat16(v);
    __nv_bfloat16 lo = __float2bfloat16(v - __bfloat162float(hi));
    size_t di = (size_t)l * 65536 + n * 256 + k;
    if (m) { g_cw2hi[di] = hi; g_cw2lo[di] = lo; }
    else   { g_cw1hi[di] = hi; g_cw1lo[di] = lo; }
}

// ---------------- pool-attn weight transpose + bf16 split --------------------
__global__ void prep_pw(const float* __restrict__ paw1) {
    int n = blockIdx.x, k = threadIdx.x;
    float v = paw1[k * 256 + n];
    __nv_bfloat16 hi = __float2bfloat16(v);
    __nv_bfloat16 lo = __float2bfloat16(v - __bfloat162float(hi));
    g_pahi[n * 256 + k] = hi;
    g_palo[n * 256 + k] = lo;
}

// ---------------- r = relu(edge_attr @ ew1 + eb1) -> fp16 (half2 stores) -----
__global__ void r_kernel(const float* __restrict__ ea, const float* __restrict__ ew1,
                         const float* __restrict__ eb1) {
    int e0 = blockIdx.x * 32;
    int j = threadIdx.x;            // 0..127 -> cols 2j, 2j+1
    __shared__ float eas[256];
    eas[j] = ea[e0 * 8 + j];
    eas[j + 128] = ea[e0 * 8 + 128 + j];
    float w0[8], w1[8];
#pragma unroll
    for (int k = 0; k < 8; k++) {
        w0[k] = ew1[k * 256 + 2 * j];
        w1[k] = ew1[k * 256 + 2 * j + 1];
    }
    float b0 = eb1[2 * j], b1 = eb1[2 * j + 1];
    __syncthreads();
    __half2* out = (__half2*)g_R16;
    for (int e = 0; e < 32; e++) {
        float a0 = b0, a1 = b1;
#pragma unroll
        for (int k = 0; k < 8; k++) {
            float v = eas[e * 8 + k];
            a0 += v * w0[k];
            a1 += v * w1[k];
        }
        out[(size_t)(e0 + e) * 128 + j] =
            __floats2half2_rn(fmaxf(a0, 0.f), fmaxf(a1, 0.f));
    }
}

// ---------------- h = silu([x|c] @ in_w + in_b); also z = h ------------------
__global__ void input_proj(const float* __restrict__ x, const float* __restrict__ c,
                           const int* __restrict__ gid, const int* __restrict__ lid,
                           const float* __restrict__ inw, const float* __restrict__ inb) {
    int n0 = blockIdx.x * 8;
    int j = threadIdx.x;
    __shared__ float xs[8 * 16];
    __shared__ float cs[8];
    if (j < 128) xs[j] = x[n0 * 16 + j];
    if (j < 8) { int n = n0 + j; cs[j] = c[gid[n] * PG + lid[n]]; }
    float w[17];
#pragma unroll
    for (int k = 0; k < 17; k++) w[k] = inw[k * 256 + j];
    float b = inb[j];
    __syncthreads();
    for (int n = 0; n < 8; n++) {
        float acc = b + cs[n] * w[16];
#pragma unroll
        for (int k = 0; k < 16; k++) acc += xs[n * 16 + k] * w[k];
        float v = siluf(acc);
        g_h[(n0 + n) * 256 + j] = v;
        g_z[(n0 + n) * 256 + j] = v;
    }
}

// ---------------- edge GEMM (single fp16 term) + fused relu-msg scatter -----
__global__ void __launch_bounds__(256, 2) edge_mma(int l, const int* __restrict__ eidx) {
    extern __shared__ char sm[];
    uint32_t sbase = smem_u32(sm);
    float* sBias = (float*)(sm + 98304);

    int tid = threadIdx.x, lane = tid & 31, wid = tid >> 5;
    int wm = wid & 3, wn = wid >> 2;
    int col0 = blockIdx.x * 128, row0 = blockIdx.y * 128;

    if (tid < 128) sBias[tid] = g_bl[l * 256 + col0 + tid];

    const uint4* Ag = (const uint4*)g_R16 + (size_t)row0 * 32;
    const uint4* Bg = (const uint4*)g_W16 + (size_t)l * 8192 + (size_t)col0 * 32;

    float acc[16][4];
#pragma unroll
    for (int i = 0; i < 16; i++) { acc[i][0] = 0.f; acc[i][1] = 0.f; acc[i][2] = 0.f; acc[i][3] = 0.f; }

    auto issue = [&](int c, int s) {
        uint32_t sa = sbase + s * 32768;
#pragma unroll
        for (int i = 0; i < 4; i++) {
            int elem = tid + 256 * i;
            int r = elem >> 3, u = elem & 7;
            uint32_t o = swz((uint32_t)(r * 128 + u * 16));
            CPA16(sa + o,         Ag + (size_t)r * 32 + c * 8 + u);
            CPA16(sa + 16384 + o, Bg + (size_t)r * 32 + c * 8 + u);
        }
    };

    issue(0, 0); CPC;
    issue(1, 1); CPC;

#pragma unroll
    for (int c = 0; c < 4; c++) {
        int s = (c < 3) ? c : 0;
        if (c < 3) { CPW1; } else { CPW0; }
        __syncthreads();
        uint32_t sa = sbase + s * 32768;
#pragma unroll
        for (int ks = 0; ks < 4; ks++) {
            uint32_t a0[4], a1[4];
            int kb = ks * 32 + ((lane >> 4) << 4);
            LDSM4(a0, sa + swz((uint32_t)((wm * 32 + (lane & 15)) * 128 + kb)));
            LDSM4(a1, sa + swz((uint32_t)((wm * 32 + 16 + (lane & 15)) * 128 + kb)));
#pragma unroll
            for (int np = 0; np < 4; np++) {
                int g = lane >> 3, li = lane & 7;
                int brow = wn * 64 + np * 16 + ((g >> 1) << 3) + li;
                int bkb = ks * 32 + ((g & 1) << 4);
                uint32_t bh[4];
                LDSM4(bh, sa + 16384 + swz((uint32_t)(brow * 128 + bkb)));
#pragma unroll
                for (int t = 0; t < 2; t++) {
                    mma_f16(acc[0 * 8 + np * 2 + t], a0, bh[2 * t], bh[2 * t + 1]);
                    mma_f16(acc[1 * 8 + np * 2 + t], a1, bh[2 * t], bh[2 * t + 1]);
                }
            }
        }
        if (c < 2) { issue(c + 2, c + 2 == 2 ? 2 : 0); CPC; }
    }

    // epilogue: relu(acc + bias + h[src]) -> paired-lane v4 red to z[dst]
    int q = lane >> 2;
    int c2 = (lane & 3) * 2;
    int src_[2][2], dst_[2][2];
#pragma unroll
    for (int mt = 0; mt < 2; mt++)
#pragma unroll
        for (int h = 0; h < 2; h++) {
            int e = row0 + wm * 32 + mt * 16 + h * 8 + q;
            src_[mt][h] = eidx[e];
            dst_[mt][h] = eidx[EE + e];
        }
#pragma unroll
    for (int mt = 0; mt < 2; mt++) {
#pragma unroll
        for (int nt = 0; nt < 8; nt++) {
            float* a = acc[mt * 8 + nt];
            int coln = wn * 64 + nt * 8 + c2;
            int col = col0 + coln;
            float2 bb = *(float2*)(sBias + coln);
#pragma unroll
            for (int h = 0; h < 2; h++) {
                const float2 hv = *(const float2*)(g_h + (size_t)src_[mt][h] * 256 + col);
                float v0 = fmaxf(a[2 * h + 0] + bb.x + hv.x, 0.f);
                float v1 = fmaxf(a[2 * h + 1] + bb.y + hv.y, 0.f);
                float e0 = __shfl_xor_sync(~0u, v0, 1);
                float e1 = __shfl_xor_sync(~0u, v1, 1);
                if (!(lane & 1)) {
                    float* zp = g_z + (size_t)dst_[mt][h] * 256 + col;
                    asm volatile("red.global.add.v4.f32 [%0], {%1,%2,%3,%4};"
                                 :: "l"(zp), "f"(v0), "f"(v1), "f"(e0), "f"(e1) : "memory");
                }
            }
        }
    }
}

// ---------------- node0: fp32 z LDG->bf16 convert GEMM (kills z_split) -------
// z(fp32, converted in-kernel) @ cw1 (bf16 hi+lo) -> silu -> thi (bf16)
// K chunks of 32, 2-stage. Stage: A-bf16 8KB @0, Bh 8KB @8192, Bl 8KB @16384.
// RACE FIX vs round 7: __syncthreads() before overwriting the just-read stage.
__global__ void __launch_bounds__(256, 2) node0_mma(int l, const float* __restrict__ cb1) {
    extern __shared__ char sm[];
    uint32_t sbase = smem_u32(sm);
    float* sBias = (float*)(sm + 2 * 24576);

    int tid = threadIdx.x, lane = tid & 31, wid = tid >> 5;
    int wm = wid & 3, wn = wid >> 2;
    int col0 = blockIdx.x * 128, row0 = blockIdx.y * 128;

    if (tid < 128) sBias[tid] = cb1[l * 256 + col0 + tid];

    const float* Az = g_z + (size_t)row0 * 256;
    const uint4* Bh4 = (const uint4*)(g_cw1hi + (size_t)l * 65536) + (size_t)col0 * 32;
    const uint4* Bl4 = (const uint4*)(g_cw1lo + (size_t)l * 65536) + (size_t)col0 * 32;

    float acc[16][4];
#pragma unroll
    for (int i = 0; i < 16; i++) { acc[i][0] = 0.f; acc[i][1] = 0.f; acc[i][2] = 0.f; acc[i][3] = 0.f; }

    float4 pa[2][2];   // [i][half]: A prefetch regs for one chunk

    auto ldgA = [&](int c) {
#pragma unroll
        for (int i = 0; i < 2; i++) {
            int elem = tid + 256 * i;
            int r = elem >> 2, u = elem & 3;
            const float* src = Az + (size_t)r * 256 + c * 32 + u * 8;
            pa[i][0] = *(const float4*)src;
            pa[i][1] = *(const float4*)(src + 4);
        }
    };
    auto stsA = [&](int s) {
#pragma unroll
        for (int i = 0; i < 2; i++) {
            int elem = tid + 256 * i;
            int r = elem >> 2, u = elem & 3;
            __nv_bfloat162 b0 = __floats2bfloat162_rn(pa[i][0].x, pa[i][0].y);
            __nv_bfloat162 b1 = __floats2bfloat162_rn(pa[i][0].z, pa[i][0].w);
            __nv_bfloat162 b2 = __floats2bfloat162_rn(pa[i][1].x, pa[i][1].y);
            __nv_bfloat162 b3 = __floats2bfloat162_rn(pa[i][1].z, pa[i][1].w);
            uint4 val;
            val.x = *(uint32_t*)&b0; val.y = *(uint32_t*)&b1;
            val.z = *(uint32_t*)&b2; val.w = *(uint32_t*)&b3;
            *(uint4*)(sm + s * 24576 + swz64((uint32_t)(r * 64 + u * 16))) = val;
        }
    };
    auto issueB = [&](int c, int s) {
        uint32_t sa = sbase + s * 24576;
#pragma unroll
        for (int i = 0; i < 2; i++) {
            int elem = tid + 256 * i;
            int r = elem >> 2, u = elem & 3;
            uint32_t o = swz64((uint32_t)(r * 64 + u * 16));
            CPA16(sa + 8192 + o,  Bh4 + (size_t)r * 32 + c * 4 + u);
            CPA16(sa + 16384 + o, Bl4 + (size_t)r * 32 + c * 4 + u);
        }
    };

    ldgA(0);
    issueB(0, 0); CPC;
    issueB(1, 1); CPC;
    stsA(0);
    ldgA(1);
    CPW1;
    __syncthreads();

#pragma unroll 1
    for (int c = 0; c < 8; c++) {
        uint32_t sa = sbase + (c & 1) * 24576;
#pragma unroll
        for (int ks = 0; ks < 2; ks++) {
            uint32_t a0[4], a1[4];
            int kb = ks * 32 + ((lane >> 4) << 4);
            LDSM4(a0, sa + swz64((uint32_t)((wm * 32 + (lane & 15)) * 64 + kb)));
            LDSM4(a1, sa + swz64((uint32_t)((wm * 32 + 16 + (lane & 15)) * 64 + kb)));
#pragma unroll
            for (int np = 0; np < 4; np++) {
                int g = lane >> 3, li = lane & 7;
                int brow = wn * 64 + np * 16 + ((g >> 1) << 3) + li;
                int bkb = ks * 32 + ((g & 1) << 4);
                uint32_t bh[4], bl[4];
                LDSM4(bh, sa + 8192 + swz64((uint32_t)(brow * 64 + bkb)));
                LDSM4(bl, sa + 16384 + swz64((uint32_t)(brow * 64 + bkb)));
#pragma unroll
                for (int t = 0; t < 2; t++) {
                    mma_bf16(acc[0 * 8 + np * 2 + t], a0, bh[2 * t], bh[2 * t + 1]);
                    mma_bf16(acc[0 * 8 + np * 2 + t], a0, bl[2 * t], bl[2 * t + 1]);
                    mma_bf16(acc[1 * 8 + np * 2 + t], a1, bh[2 * t], bh[2 * t + 1]);
                    mma_bf16(acc[1 * 8 + np * 2 + t], a1, bl[2 * t], bl[2 * t + 1]);
                }
            }
        }
        if (c < 7) {
            __syncthreads();                 // all readers done with stage c&1
            stsA((c + 1) & 1);
            if (c < 6) { ldgA(c + 2); issueB(c + 2, c & 1); CPC; CPW1; }
            else       { CPW0; }
            __syncthreads();
        }
    }

    int q = lane >> 2;
    int c2 = (lane & 3) * 2;
#pragma unroll
    for (int mt = 0; mt < 2; mt++) {
#pragma unroll
        for (int nt = 0; nt < 8; nt++) {
            float* a = acc[mt * 8 + nt];
            int coln = wn * 64 + nt * 8 + c2;
            int col = col0 + coln;
            float2 bb = *(float2*)(sBias + coln);
#pragma unroll
            for (int h = 0; h < 2; h++) {
                int rr = row0 + wm * 32 + mt * 16 + h * 8 + q;
                float v0 = siluf(a[2 * h + 0] + bb.x);
                float v1 = siluf(a[2 * h + 1] + bb.y);
                *(__nv_bfloat162*)(g_thi + (size_t)rr * 256 + col) =
                    __nv_bfloat162(__float2bfloat16(v0), __float2bfloat16(v1));
            }
        }
    }
}

// ---------------- node GEMM: bf16 A, W hi+lo (2-term), 2-stage cp.async ------
// MODE 1: thi @ cw2 -> g_hn (fp32).
// MODE 2: zhi(final h) @ paw1 -> tanh -> dot paw2 -> atomicAdd g_scores.
template <int MODE>
__global__ void __launch_bounds__(256, 2) node_mma(int l, const float* __restrict__ bias_all,
                                                   const float* __restrict__ w2) {
    extern __shared__ char sm[];
    uint32_t sbase = smem_u32(sm);
    float* sBias = (float*)(sm + 98304);
    float* sW2 = (float*)(sm + 98304 + 512);

    const __nv_bfloat16* A = (MODE == 1) ? g_thi : g_zhi;
    const __nv_bfloat16* Bhi = (MODE == 1) ? (g_cw2hi + (size_t)l * 65536) : g_pahi;
    const __nv_bfloat16* Blo = (MODE == 1) ? (g_cw2lo + (size_t)l * 65536) : g_palo;
    const float* bias = bias_all + l * 256;

    int tid = threadIdx.x, lane = tid & 31, wid = tid >> 5;
    int wm = wid & 3, wn = wid >> 2;
    int col0 = blockIdx.x * 128, row0 = blockIdx.y * 128;

    if (tid < 128) sBias[tid] = bias[col0 + tid];
    if (MODE == 2 && tid < 128) sW2[tid] = w2[col0 + tid];

    const uint4* A4 = (const uint4*)A + (size_t)row0 * 32;
    const uint4* Bh4 = (const uint4*)Bhi + (size_t)col0 * 32;
    const uint4* Bl4 = (const uint4*)Blo + (size_t)col0 * 32;

    float acc[16][4];
#pragma unroll
    for (int i = 0; i < 16; i++) { acc[i][0] = 0.f; acc[i][1] = 0.f; acc[i][2] = 0.f; acc[i][3] = 0.f; }

    auto issue = [&](int c, int s) {
        uint32_t sa = sbase + s * 49152;
#pragma unroll
        for (int i = 0; i < 4; i++) {
            int elem = tid + 256 * i;
            int r = elem >> 3, u = elem & 7;
            uint32_t o = swz((uint32_t)(r * 128 + u * 16));
            CPA16(sa + o,         A4  + (size_t)r * 32 + c * 8 + u);
            CPA16(sa + 16384 + o, Bh4 + (size_t)r * 32 + c * 8 + u);
            CPA16(sa + 32768 + o, Bl4 + (size_t)r * 32 + c * 8 + u);
        }
    };

    issue(0, 0); CPC;
    issue(1, 1); CPC;

#pragma unroll
    for (int c = 0; c < 4; c++) {
        if (c < 3) { CPW1; } else { CPW0; }
        __syncthreads();
        uint32_t sa = sbase + (c & 1) * 49152;
#pragma unroll
        for (int ks = 0; ks < 4; ks++) {
            uint32_t a0[4], a1[4];
            int kb = ks * 32 + ((lane >> 4) << 4);
            LDSM4(a0, sa + swz((uint32_t)((wm * 32 + (lane & 15)) * 128 + kb)));
            LDSM4(a1, sa + swz((uint32_t)((wm * 32 + 16 + (lane & 15)) * 128 + kb)));
#pragma unroll
            for (int np = 0; np < 4; np++) {
                int g = lane >> 3, li = lane & 7;
                int brow = wn * 64 + np * 16 + ((g >> 1) << 3) + li;
                int bkb = ks * 32 + ((g & 1) << 4);
                uint32_t bh[4], bl[4];
                LDSM4(bh, sa + 16384 + swz((uint32_t)(brow * 128 + bkb)));
                LDSM4(bl, sa + 32768 + swz((uint32_t)(brow * 128 + bkb)));
#pragma unroll
                for (int t = 0; t < 2; t++) {
                    mma_bf16(acc[0 * 8 + np * 2 + t], a0, bh[2 * t], bh[2 * t + 1]);
                    mma_bf16(acc[0 * 8 + np * 2 + t], a0, bl[2 * t], bl[2 * t + 1]);
                    mma_bf16(acc[1 * 8 + np * 2 + t], a1, bh[2 * t], bh[2 * t + 1]);
                    mma_bf16(acc[1 * 8 + np * 2 + t], a1, bl[2 * t], bl[2 * t + 1]);
                }
            }
        }
        if (c < 2) { __syncthreads(); issue(c + 2, c & 1); CPC; }
    }

    int q = lane >> 2;
    int c2 = (lane & 3) * 2;
    if (MODE == 1) {
#pragma unroll
        for (int mt = 0; mt < 2; mt++) {
#pragma unroll
            for (int nt = 0; nt < 8; nt++) {
                float* a = acc[mt * 8 + nt];
                int coln = wn * 64 + nt * 8 + c2;
                int col = col0 + coln;
                float2 bb = *(float2*)(sBias + coln);
#pragma unroll
                for (int h = 0; h < 2; h++) {
                    int rr = row0 + wm * 32 + mt * 16 + h * 8 + q;
                    float v0 = a[2 * h + 0] + bb.x;
                    float v1 = a[2 * h + 1] + bb.y;
                    if (rr < NN) *(float2*)(g_hn + (size_t)rr * 256 + col) = make_float2(v0, v1);
                }
            }
        }
    } else {
#pragma unroll
        for (int mt = 0; mt < 2; mt++) {
#pragma unroll
            for (int h = 0; h < 2; h++) {
                int rr = row0 + wm * 32 + mt * 16 + h * 8 + q;
                float part = 0.f;
#pragma unroll
                for (int nt = 0; nt < 8; nt++) {
                    float* a = acc[mt * 8 + nt];
                    int coln = wn * 64 + nt * 8 + c2;
                    part += tanhf(a[2 * h + 0] + sBias[coln])     * sW2[coln];
                    part += tanhf(a[2 * h + 1] + sBias[coln + 1]) * sW2[coln + 1];
                }
                part += __shfl_xor_sync(~0u, part, 1);
                part += __shfl_xor_sync(~0u, part, 2);
                if ((lane & 3) == 0 && rr < NN) atomicAdd(&g_scores[rr], part);
            }
        }
    }
}

// ---------------- LayerNorm + residual silu update; z = h_next; bf16 h -------
__global__ void ln_update(int l, const float* __restrict__ lng, const float* __restrict__ lnb) {
    int warp = threadIdx.x >> 5, lane = threadIdx.x & 31;
    int n = blockIdx.x * 8 + warp;
    const float* g = lng + l * 256;
    const float* b = lnb + l * 256;
    const float* row = g_hn + (size_t)n * 256;
    float v[8];
    float s = 0.f, ss = 0.f;
#pragma unroll
    for (int t = 0; t < 8; t++) {
        v[t] = row[lane + 32 * t];
        s += v[t]; ss += v[t] * v[t];
    }
#pragma unroll
    for (int o = 16; o > 0; o >>= 1) {
        s += __shfl_xor_sync(~0u, s, o);
        ss += __shfl_xor_sync(~0u, ss, o);
    }
    float m = s * (1.f / 256.f);
    float var = ss * (1.f / 256.f) - m * m;
    float r = rsqrtf(var + 1e-5f);
    float* hrow = g_h + (size_t)n * 256;
    float* zrow = g_z + (size_t)n * 256;
#pragma unroll
    for (int t = 0; t < 8; t++) {
        int cidx = lane + 32 * t;
        float u = (v[t] - m) * r * g[cidx] + b[cidx];
        float nh = hrow[cidx] + siluf(u);
        hrow[cidx] = nh;
        zrow[cidx] = nh;
        if (l == LL - 1) g_zhi[(size_t)n * 256 + cidx] = __float2bfloat16(nh);
    }
}

// ---------------- init scores to pab2 ----------------------------------------
__global__ void init_scores(const float* __restrict__ pab2) {
    int i = blockIdx.x * 256 + threadIdx.x;
    if (i < NN) g_scores[i] = pab2[0];
}

// ---------------- global softmax stats --------------------------------------
__global__ void softmax_stats() {
    __shared__ float red[1024];
    int t = threadIdx.x;
    float m = -1e30f;
    for (int i = t; i < NN; i += 1024) m = fmaxf(m, g_scores[i]);
    red[t] = m;
    __syncthreads();
    for (int o = 512; o > 0; o >>= 1) {
        if (t < o) red[t] = fmaxf(red[t], red[t + o]);
        __syncthreads();
    }
    float gmax = red[0];
    __syncthreads();
    float s = 0.f;
    for (int i = t; i < NN; i += 1024) s += expf(g_scores[i] - gmax);
    red[t] = s;
    __syncthreads();
    for (int o = 512; o > 0; o >>= 1) {
        if (t < o) red[t] += red[t + o];
        __syncthreads();
    }
    if (t == 0) { g_stats[0] = gmax; g_stats[1] = red[0]; }
}

// ---------------- per-graph renormalized attention --------------------------
__global__ void seg_attn() {
    int g = blockIdx.x, t = threadIdx.x;
    float gmax = g_stats[0], Z = g_stats[1];
    int base = g * PG;
    float s = 0.f;
    for (int i = t; i < PG; i += 256) s += expf(g_scores[base + i] - gmax);
    __shared__ float red[256];
    red[t] = s;
    __syncthreads();
    for (int o = 128; o > 0; o >>= 1) {
        if (t < o) red[t] += red[t + o];
        __syncthreads();
    }
    float denom = red[0] / Z + 1e-8f;
    float scale = 1.f / (Z * denom);
    for (int i = t; i < PG; i += 256) g_attn[base + i] = expf(g_scores[base + i] - gmax) * scale;
    g_pooled[g * 256 + t] = 0.f;
}

// ---------------- weighted pooling ------------------------------------------
__global__ void pool_kernel() {
    int g = blockIdx.x, chunk = blockIdx.y, j = threadIdx.x;
    int base = g * PG + chunk * 250;
    float acc = 0.f;
    for (int i = 0; i < 250; i++)
        acc += g_h[(size_t)(base + i) * 256 + j] * g_attn[base + i];
    atomicAdd(&g_pooled[g * 256 + j], acc);
}

// ---------------- head -------------------------------------------------------
__global__ void head_kernel(const float* __restrict__ hw1, const float* __restrict__ hb1,
                            const float* __restrict__ hw2, const float* __restrict__ hb2,
                            float* __restrict__ out) {
    int g = blockIdx.x, j = threadIdx.x;
    __shared__ float ps[256];
    __shared__ float red[256];
    ps[j] = g_pooled[g * 256 + j];
    __syncthreads();
    float acc = hb1[j];
#pragma unroll 8
    for (int k = 0; k < 256; k++) acc += ps[k] * hw1[k * 256 + j];
    red[j] = siluf(acc) * hw2[j];
    __syncthreads();
    for (int o = 128; o > 0; o >>= 1) {
        if (j < o) red[j] += red[j + o];
        __syncthreads();
    }
    if (j == 0) out[g] = red[0] + hb2[0];
}

// ---------------- launch -----------------------------------------------------
extern "C" void kernel_launch(void* const* d_in, const int* in_sizes, int n_in,
                              void* d_out, int out_size) {
    const float* x    = (const float*)d_in[0];
    const float* ea   = (const float*)d_in[1];
    const float* c    = (const float*)d_in[2];
    const int*   eidx = (const int*)  d_in[3];
    const int*   gid  = (const int*)  d_in[4];
    const int*   lid  = (const int*)  d_in[5];
    const float* ew1  = (const float*)d_in[6];
    const float* eb1  = (const float*)d_in[7];
    const float* ew2  = (const float*)d_in[8];
    const float* eb2  = (const float*)d_in[9];
    const float* inw  = (const float*)d_in[10];
    const float* inb  = (const float*)d_in[11];
    const float* lin_w = (const float*)d_in[12];
    const float* lin_b = (const float*)d_in[13];
    const float* cw1  = (const float*)d_in[14];
    const float* cb1  = (const float*)d_in[15];
    const float* cw2  = (const float*)d_in[16];
    const float* cb2  = (const float*)d_in[17];
    const float* lng  = (const float*)d_in[18];
    const float* lnb  = (const float*)d_in[19];
    const float* paw1 = (const float*)d_in[20];
    const float* pab1 = (const float*)d_in[21];
    const float* paw2 = (const float*)d_in[22];
    const float* pab2 = (const float*)d_in[23];
    const float* hw1  = (const float*)d_in[24];
    const float* hb1  = (const float*)d_in[25];
    const float* hw2  = (const float*)d_in[26];
    const float* hb2  = (const float*)d_in[27];
    float* out = (float*)d_out;

    static int attr_done = 0;
    if (!attr_done) {
        cudaFuncSetAttribute((const void*)edge_mma,
                             cudaFuncAttributeMaxDynamicSharedMemorySize, PIPE_SMEM);
        cudaFuncSetAttribute((const void*)node0_mma,
                             cudaFuncAttributeMaxDynamicSharedMemorySize, NODE0_SMEM);
        cudaFuncSetAttribute((const void*)node_mma<1>,
                             cudaFuncAttributeMaxDynamicSharedMemorySize, PIPE_SMEM);
        cudaFuncSetAttribute((const void*)node_mma<2>,
                             cudaFuncAttributeMaxDynamicSharedMemorySize, PIPE_SMEM);
        attr_done = 1;
    }

    prep_W<<<LL * 256, 256>>>(ew2, lin_w);
    prep_bl<<<LL, 256>>>(eb2, lin_w, lin_b);
    prep_nw<<<dim3(256, LL, 2), 256>>>(cw1, cw2);
    prep_pw<<<256, 256>>>(paw1);
    r_kernel<<<EE / 32, 128>>>(ea, ew1, eb1);
    input_proj<<<NN / 8, 256>>>(x, c, gid, lid, inw, inb);

    for (int l = 0; l < LL; l++) {
        edge_mma<<<dim3(2, EE / 128), 256, PIPE_SMEM>>>(l, eidx);
        node0_mma<<<dim3(2, NPAD / 128), 256, NODE0_SMEM>>>(l, cb1);
        node_mma<1><<<dim3(2, NPAD / 128), 256, PIPE_SMEM>>>(l, cb2, (const float*)0);
        ln_update<<<NN / 8, 256>>>(l, lng, lnb);
    }

    init_scores<<<(NN + 255) / 256, 256>>>(pab2);
    node_mma<2><<<dim3(2, NPAD / 128), 256, PIPE_SMEM>>>(0, pab1, paw2);
    softmax_stats<<<1, 1024>>>();
    seg_attn<<<GB, 256>>>();
    pool_kernel<<<dim3(GB, 4), 256>>>();
    head_kernel<<<GB, 256>>>(hw1, hb1, hw2, hb2, out);
    (void)in_sizes; (void)n_in; (void)out_size;
}